// round 1
// baseline (speedup 1.0000x reference)
#include <cuda_runtime.h>
#include <cstdint>

// Problem constants
#define BB   32
#define CC   16
#define UU   16
#define LL   128
#define PW   (LL*LL)        // 16384
#define KP   5              // POWERS
#define MKC  80             // k*c  (=POWERS*C)
#define MLU  80             // l*u  (=POWERS*U)

// Scratch: t1[b][k][c][p][w], s[b][l][u][p][w]  (167 MB each, zero-init .bss)
__device__ float g_t1[BB * KP * CC * PW];
__device__ float g_s [BB * KP * UU * PW];

// ---------- packed fp32x2 helpers (sm_100+/sm_103a) ----------
__device__ __forceinline__ unsigned long long pack2(float lo, float hi) {
    unsigned long long r;
    asm("mov.b64 %0, {%1,%2};" : "=l"(r) : "f"(lo), "f"(hi));
    return r;
}
__device__ __forceinline__ void fma2(unsigned long long& d, unsigned long long a, unsigned long long b) {
    asm("fma.rn.f32x2 %0, %1, %2, %0;" : "+l"(d) : "l"(a), "l"(b));
}
__device__ __forceinline__ float2 unpack2(unsigned long long v) {
    float2 f;
    asm("mov.b64 {%0,%1}, %2;" : "=f"(f.x), "=f"(f.y) : "l"(v));
    return f;
}

// ============================================================================
// Stage 1: t1[b,k,c,p,w] = sum_h cheb1[k,h,p] * x[b,c,h,w]
// One block per (b,c,k): C[p,w] = A^T B with A=cheb1[k] ([h][p]), B=x[b,c] ([h][w])
// ============================================================================
__global__ __launch_bounds__(256, 2) void stage1_kernel(
    const float* __restrict__ x, const float* __restrict__ cheb1)
{
    __shared__ float As[16][132];
    __shared__ float Bs[16][132];

    int bid = blockIdx.x;
    int k = bid % KP;
    int c = (bid / KP) % CC;
    int b = bid / (KP * CC);

    const float* A  = cheb1 + k * PW;                  // [h][p]
    const float* Bm = x + (b * CC + c) * PW;           // [h][w]
    float* Cm = g_t1 + ((b * KP + k) * CC + c) * PW;   // [p][w]

    int tid = threadIdx.x;
    int tx = tid & 15;        // column group (w)
    int ty = tid >> 4;        // row group (p)

    unsigned long long acc[8][4];
#pragma unroll
    for (int i = 0; i < 8; i++)
#pragma unroll
        for (int j = 0; j < 4; j++) acc[i][j] = 0ull;

    for (int h0 = 0; h0 < LL; h0 += 16) {
#pragma unroll
        for (int t = 0; t < 2; t++) {
            int idx = tid + t * 256;          // 512 float4s per operand
            int r = idx >> 5;
            int c4 = (idx & 31) << 2;
            float4 va = *(const float4*)(A  + (h0 + r) * LL + c4);
            float4 vb = *(const float4*)(Bm + (h0 + r) * LL + c4);
            *(float4*)(&As[r][c4]) = va;
            *(float4*)(&Bs[r][c4]) = vb;
        }
        __syncthreads();

#pragma unroll
        for (int hh = 0; hh < 16; hh++) {
            float4 a0 = *(const float4*)(&As[hh][ty * 8]);
            float4 a1 = *(const float4*)(&As[hh][ty * 8 + 4]);
            float4 b0 = *(const float4*)(&Bs[hh][tx * 8]);
            float4 b1 = *(const float4*)(&Bs[hh][tx * 8 + 4]);
            unsigned long long bp[4] = {
                pack2(b0.x, b0.y), pack2(b0.z, b0.w),
                pack2(b1.x, b1.y), pack2(b1.z, b1.w)
            };
            float av[8] = {a0.x, a0.y, a0.z, a0.w, a1.x, a1.y, a1.z, a1.w};
#pragma unroll
            for (int i = 0; i < 8; i++) {
                unsigned long long ap = pack2(av[i], av[i]);
#pragma unroll
                for (int j = 0; j < 4; j++) fma2(acc[i][j], ap, bp[j]);
            }
        }
        __syncthreads();
    }

#pragma unroll
    for (int i = 0; i < 8; i++) {
        float2 p0 = unpack2(acc[i][0]), p1 = unpack2(acc[i][1]);
        float2 p2 = unpack2(acc[i][2]), p3 = unpack2(acc[i][3]);
        float4 o0 = make_float4(p0.x, p0.y, p1.x, p1.y);
        float4 o1 = make_float4(p2.x, p2.y, p3.x, p3.y);
        float* row = Cm + (ty * 8 + i) * LL + tx * 8;
        *(float4*)(row)     = o0;
        *(float4*)(row + 4) = o1;
    }
}

// ============================================================================
// Stage 2: s[b, (l,u), pix] = sum_{(k,c)} Cmat[(k,c),(l,u)] * t1[b,(k,c),pix]
// Cmat[k'][m] = coefs[k1, l, c, u] with k'=(k1*16+c), m=(l*16+u)
// Block: one batch b, 128-pixel tile. Dynamic smem: Cs[80*80] + Ts[80][132]
// ============================================================================
#define S2_SMEM_FLOATS (MKC * MLU + MKC * 132)
__global__ __launch_bounds__(256, 3) void stage2_kernel(const float* __restrict__ coefs)
{
    extern __shared__ float sm2[];
    float* Cs = sm2;                 // [k'][m], 80x80
    float* Ts = sm2 + MKC * MLU;     // [k'][pix], 80x132 (padded)

    int b    = blockIdx.y;
    int pix0 = blockIdx.x * 128;
    int tid  = threadIdx.x;
    int mg = tid >> 5;               // 8 groups * 10 m each = 80
    int tn = tid & 31;               // 32 threads * 4 pixels = 128

    // Load Cmat (6400 = 25 * 256)
#pragma unroll
    for (int t = 0; t < 25; t++) {
        int idx = tid + t * 256;
        int kk = idx / MLU;      // k' = k1*16+c
        int m  = idx % MLU;      // m  = l*16+u
        int k1 = kk >> 4, c = kk & 15;
        int l  = m >> 4,  u = m & 15;
        Cs[idx] = coefs[((k1 * KP + l) * CC + c) * UU + u];
    }
    // Load t1 tile: 80 rows x 128 pixels
    const float* Tb = g_t1 + b * MKC * PW + pix0;
#pragma unroll
    for (int t = 0; t < 10; t++) {
        int idx = tid + t * 256;     // 2560 float4s
        int r = idx >> 5;
        int c4 = (idx & 31) << 2;
        *(float4*)(&Ts[r * 132 + c4]) = *(const float4*)(Tb + r * PW + c4);
    }
    __syncthreads();

    unsigned long long acc[10][2];
#pragma unroll
    for (int i = 0; i < 10; i++) { acc[i][0] = 0ull; acc[i][1] = 0ull; }

#pragma unroll 4
    for (int kk = 0; kk < MKC; kk++) {
        float4 bv = *(const float4*)(&Ts[kk * 132 + tn * 4]);
        unsigned long long b0 = pack2(bv.x, bv.y);
        unsigned long long b1 = pack2(bv.z, bv.w);
        const float* crow = Cs + kk * MLU + mg * 10;
#pragma unroll
        for (int i = 0; i < 10; i++) {
            unsigned long long ap = pack2(crow[i], crow[i]);
            fma2(acc[i][0], ap, b0);
            fma2(acc[i][1], ap, b1);
        }
    }

    float* Sb = g_s + b * MLU * PW + pix0 + tn * 4;
#pragma unroll
    for (int i = 0; i < 10; i++) {
        float2 p0 = unpack2(acc[i][0]), p1 = unpack2(acc[i][1]);
        float4 v = make_float4(p0.x, p0.y, p1.x, p1.y);
        *(float4*)(Sb + (mg * 10 + i) * PW) = v;
    }
}

// ============================================================================
// Stage 3: out[b,u,p,q] = sum_{l,w} s[b,l,u,p,w] * cheb2[l,w,q]
// One block per (b,u): NN GEMM, M=128(p), N=128(q), K=640 (l,w)
// A transposed on load into As[w][p] (132-pad), B=cheb2[l] copied direct.
// ============================================================================
__global__ __launch_bounds__(256, 2) void stage3_kernel(
    const float* __restrict__ cheb2, float* __restrict__ out)
{
    __shared__ float As[16][132];
    __shared__ float Bs[16][132];

    int bid = blockIdx.x;
    int u = bid % UU;
    int b = bid / UU;

    float* Cm = out + (b * UU + u) * PW;

    int tid = threadIdx.x;
    int tx = tid & 15;
    int ty = tid >> 4;

    unsigned long long acc[8][4];
#pragma unroll
    for (int i = 0; i < 8; i++)
#pragma unroll
        for (int j = 0; j < 4; j++) acc[i][j] = 0ull;

    for (int k0 = 0; k0 < KP * LL; k0 += 16) {
        int l  = k0 >> 7;        // which cheb order
        int w0 = k0 & 127;       // w offset within it
        const float* Aslice = g_s + ((b * KP + l) * UU + u) * PW;  // [p][w]
        const float* Bslice = cheb2 + l * PW;                       // [w][q]

        // A: load [128p x 16w], transpose into As[w][p]
#pragma unroll
        for (int t = 0; t < 2; t++) {
            int idx = tid + t * 256;      // 512 float4s
            int p  = idx >> 2;
            int w4 = (idx & 3) << 2;
            float4 va = *(const float4*)(Aslice + p * LL + w0 + w4);
            As[w4 + 0][p] = va.x;
            As[w4 + 1][p] = va.y;
            As[w4 + 2][p] = va.z;
            As[w4 + 3][p] = va.w;
        }
        // B: direct copy [16w x 128q]
#pragma unroll
        for (int t = 0; t < 2; t++) {
            int idx = tid + t * 256;
            int r = idx >> 5;
            int c4 = (idx & 31) << 2;
            *(float4*)(&Bs[r][c4]) = *(const float4*)(Bslice + (w0 + r) * LL + c4);
        }
        __syncthreads();

#pragma unroll
        for (int hh = 0; hh < 16; hh++) {
            float4 a0 = *(const float4*)(&As[hh][ty * 8]);
            float4 a1 = *(const float4*)(&As[hh][ty * 8 + 4]);
            float4 b0 = *(const float4*)(&Bs[hh][tx * 8]);
            float4 b1 = *(const float4*)(&Bs[hh][tx * 8 + 4]);
            unsigned long long bp[4] = {
                pack2(b0.x, b0.y), pack2(b0.z, b0.w),
                pack2(b1.x, b1.y), pack2(b1.z, b1.w)
            };
            float av[8] = {a0.x, a0.y, a0.z, a0.w, a1.x, a1.y, a1.z, a1.w};
#pragma unroll
            for (int i = 0; i < 8; i++) {
                unsigned long long ap = pack2(av[i], av[i]);
#pragma unroll
                for (int j = 0; j < 4; j++) fma2(acc[i][j], ap, bp[j]);
            }
        }
        __syncthreads();
    }

#pragma unroll
    for (int i = 0; i < 8; i++) {
        float2 p0 = unpack2(acc[i][0]), p1 = unpack2(acc[i][1]);
        float2 p2 = unpack2(acc[i][2]), p3 = unpack2(acc[i][3]);
        float4 o0 = make_float4(p0.x, p0.y, p1.x, p1.y);
        float4 o1 = make_float4(p2.x, p2.y, p3.x, p3.y);
        float* row = Cm + (ty * 8 + i) * LL + tx * 8;
        *(float4*)(row)     = o0;
        *(float4*)(row + 4) = o1;
    }
}

// ============================================================================
extern "C" void kernel_launch(void* const* d_in, const int* in_sizes, int n_in,
                              void* d_out, int out_size)
{
    // Identify inputs by element count (robust to ordering of the two cheb tensors,
    // which contain identical data anyway).
    const float* x = nullptr;
    const float* coefs = nullptr;
    const float* cheb1 = nullptr;
    const float* cheb2 = nullptr;
    for (int i = 0; i < n_in; i++) {
        int sz = in_sizes[i];
        const float* p = (const float*)d_in[i];
        if (sz == BB * CC * PW)          x = p;
        else if (sz == KP * KP * CC * UU) coefs = p;
        else if (sz == KP * PW) {
            if (!cheb1) cheb1 = p; else cheb2 = p;
        }
    }
    if (!cheb2) cheb2 = cheb1;
    float* out = (float*)d_out;

    // Dynamic smem for stage 2 (66.25 KB > 48 KB static limit).
    // cudaFuncSetAttribute is not stream-ordered; legal during graph capture.
    cudaFuncSetAttribute(stage2_kernel,
                         cudaFuncAttributeMaxDynamicSharedMemorySize,
                         S2_SMEM_FLOATS * (int)sizeof(float));

    stage1_kernel<<<BB * CC * KP, 256>>>(x, cheb1);
    stage2_kernel<<<dim3(PW / 128, BB), 256, S2_SMEM_FLOATS * sizeof(float)>>>(coefs);
    stage3_kernel<<<BB * UU, 256>>>(cheb2, out);
}

// round 2
// speedup vs baseline: 1.0009x; 1.0009x over previous
#include <cuda_runtime.h>
#include <cstdint>

// Problem constants
#define BB   32
#define CC   16
#define UU   16
#define LL   128
#define PW   (LL*LL)        // 16384
#define KP   5              // POWERS
#define MKC  80             // k*c  (=POWERS*C)
#define MLU  80             // l*u  (=POWERS*U)

// Scratch: t1[b][k][c][p][w], s[b][l][u][p][w]  (167 MB each, zero-init .bss)
__device__ float g_t1[BB * KP * CC * PW];
__device__ float g_s [BB * KP * UU * PW];

// ---------- packed fp32x2 helpers (sm_100+/sm_103a) ----------
__device__ __forceinline__ unsigned long long pack2(float lo, float hi) {
    unsigned long long r;
    asm("mov.b64 %0, {%1,%2};" : "=l"(r) : "f"(lo), "f"(hi));
    return r;
}
__device__ __forceinline__ void fma2(unsigned long long& d, unsigned long long a, unsigned long long b) {
    asm("fma.rn.f32x2 %0, %1, %2, %0;" : "+l"(d) : "l"(a), "l"(b));
}
__device__ __forceinline__ float2 unpack2(unsigned long long v) {
    float2 f;
    asm("mov.b64 {%0,%1}, %2;" : "=f"(f.x), "=f"(f.y) : "l"(v));
    return f;
}

// ============================================================================
// Stage 1: t1[b,k,c,p,w] = sum_h cheb1[k,h,p] * x[b,c,h,w]
// One block per (b,c,k): C[p,w] = A^T B with A=cheb1[k] ([h][p]), B=x[b,c] ([h][w])
// ============================================================================
__global__ __launch_bounds__(256, 2) void stage1_kernel(
    const float* __restrict__ x, const float* __restrict__ cheb1)
{
    __shared__ float As[16][132];
    __shared__ float Bs[16][132];

    int bid = blockIdx.x;
    int k = bid % KP;
    int c = (bid / KP) % CC;
    int b = bid / (KP * CC);

    const float* A  = cheb1 + k * PW;                  // [h][p]
    const float* Bm = x + (b * CC + c) * PW;           // [h][w]
    float* Cm = g_t1 + ((b * KP + k) * CC + c) * PW;   // [p][w]

    int tid = threadIdx.x;
    int tx = tid & 15;        // column group (w)
    int ty = tid >> 4;        // row group (p)

    unsigned long long acc[8][4];
#pragma unroll
    for (int i = 0; i < 8; i++)
#pragma unroll
        for (int j = 0; j < 4; j++) acc[i][j] = 0ull;

    for (int h0 = 0; h0 < LL; h0 += 16) {
#pragma unroll
        for (int t = 0; t < 2; t++) {
            int idx = tid + t * 256;          // 512 float4s per operand
            int r = idx >> 5;
            int c4 = (idx & 31) << 2;
            float4 va = *(const float4*)(A  + (h0 + r) * LL + c4);
            float4 vb = *(const float4*)(Bm + (h0 + r) * LL + c4);
            *(float4*)(&As[r][c4]) = va;
            *(float4*)(&Bs[r][c4]) = vb;
        }
        __syncthreads();

#pragma unroll
        for (int hh = 0; hh < 16; hh++) {
            float4 a0 = *(const float4*)(&As[hh][ty * 8]);
            float4 a1 = *(const float4*)(&As[hh][ty * 8 + 4]);
            float4 b0 = *(const float4*)(&Bs[hh][tx * 8]);
            float4 b1 = *(const float4*)(&Bs[hh][tx * 8 + 4]);
            unsigned long long bp[4] = {
                pack2(b0.x, b0.y), pack2(b0.z, b0.w),
                pack2(b1.x, b1.y), pack2(b1.z, b1.w)
            };
            float av[8] = {a0.x, a0.y, a0.z, a0.w, a1.x, a1.y, a1.z, a1.w};
#pragma unroll
            for (int i = 0; i < 8; i++) {
                unsigned long long ap = pack2(av[i], av[i]);
#pragma unroll
                for (int j = 0; j < 4; j++) fma2(acc[i][j], ap, bp[j]);
            }
        }
        __syncthreads();
    }

#pragma unroll
    for (int i = 0; i < 8; i++) {
        float2 p0 = unpack2(acc[i][0]), p1 = unpack2(acc[i][1]);
        float2 p2 = unpack2(acc[i][2]), p3 = unpack2(acc[i][3]);
        float4 o0 = make_float4(p0.x, p0.y, p1.x, p1.y);
        float4 o1 = make_float4(p2.x, p2.y, p3.x, p3.y);
        float* row = Cm + (ty * 8 + i) * LL + tx * 8;
        *(float4*)(row)     = o0;
        *(float4*)(row + 4) = o1;
    }
}

// ============================================================================
// Stage 2: s[b, (l,u), pix] = sum_{(k,c)} Cmat[(k,c),(l,u)] * t1[b,(k,c),pix]
// Cmat[k'][m] = coefs[k1, l, c, u] with k'=(k1*16+c), m=(l*16+u)
// Block: one batch b, 128-pixel tile. Dynamic smem: Cs[80*80] + Ts[80][132]
// ============================================================================
#define S2_SMEM_FLOATS (MKC * MLU + MKC * 132)
__global__ __launch_bounds__(256, 3) void stage2_kernel(const float* __restrict__ coefs)
{
    extern __shared__ float sm2[];
    float* Cs = sm2;                 // [k'][m], 80x80
    float* Ts = sm2 + MKC * MLU;     // [k'][pix], 80x132 (padded)

    int b    = blockIdx.y;
    int pix0 = blockIdx.x * 128;
    int tid  = threadIdx.x;
    int mg = tid >> 5;               // 8 groups * 10 m each = 80
    int tn = tid & 31;               // 32 threads * 4 pixels = 128

    // Load Cmat (6400 = 25 * 256)
#pragma unroll
    for (int t = 0; t < 25; t++) {
        int idx = tid + t * 256;
        int kk = idx / MLU;      // k' = k1*16+c
        int m  = idx % MLU;      // m  = l*16+u
        int k1 = kk >> 4, c = kk & 15;
        int l  = m >> 4,  u = m & 15;
        Cs[idx] = coefs[((k1 * KP + l) * CC + c) * UU + u];
    }
    // Load t1 tile: 80 rows x 128 pixels
    const float* Tb = g_t1 + b * MKC * PW + pix0;
#pragma unroll
    for (int t = 0; t < 10; t++) {
        int idx = tid + t * 256;     // 2560 float4s
        int r = idx >> 5;
        int c4 = (idx & 31) << 2;
        *(float4*)(&Ts[r * 132 + c4]) = *(const float4*)(Tb + r * PW + c4);
    }
    __syncthreads();

    unsigned long long acc[10][2];
#pragma unroll
    for (int i = 0; i < 10; i++) { acc[i][0] = 0ull; acc[i][1] = 0ull; }

#pragma unroll 4
    for (int kk = 0; kk < MKC; kk++) {
        float4 bv = *(const float4*)(&Ts[kk * 132 + tn * 4]);
        unsigned long long b0 = pack2(bv.x, bv.y);
        unsigned long long b1 = pack2(bv.z, bv.w);
        const float* crow = Cs + kk * MLU + mg * 10;
#pragma unroll
        for (int i = 0; i < 10; i++) {
            unsigned long long ap = pack2(crow[i], crow[i]);
            fma2(acc[i][0], ap, b0);
            fma2(acc[i][1], ap, b1);
        }
    }

    float* Sb = g_s + b * MLU * PW + pix0 + tn * 4;
#pragma unroll
    for (int i = 0; i < 10; i++) {
        float2 p0 = unpack2(acc[i][0]), p1 = unpack2(acc[i][1]);
        float4 v = make_float4(p0.x, p0.y, p1.x, p1.y);
        *(float4*)(Sb + (mg * 10 + i) * PW) = v;
    }
}

// ============================================================================
// Stage 3: out[b,u,p,q] = sum_{l,w} s[b,l,u,p,w] * cheb2[l,w,q]
// One block per (b,u): NN GEMM, M=128(p), N=128(q), K=640 (l,w)
// A transposed on load into As[w][p] (132-pad), B=cheb2[l] copied direct.
// ============================================================================
__global__ __launch_bounds__(256, 2) void stage3_kernel(
    const float* __restrict__ cheb2, float* __restrict__ out)
{
    __shared__ float As[16][132];
    __shared__ float Bs[16][132];

    int bid = blockIdx.x;
    int u = bid % UU;
    int b = bid / UU;

    float* Cm = out + (b * UU + u) * PW;

    int tid = threadIdx.x;
    int tx = tid & 15;
    int ty = tid >> 4;

    unsigned long long acc[8][4];
#pragma unroll
    for (int i = 0; i < 8; i++)
#pragma unroll
        for (int j = 0; j < 4; j++) acc[i][j] = 0ull;

    for (int k0 = 0; k0 < KP * LL; k0 += 16) {
        int l  = k0 >> 7;        // which cheb order
        int w0 = k0 & 127;       // w offset within it
        const float* Aslice = g_s + ((b * KP + l) * UU + u) * PW;  // [p][w]
        const float* Bslice = cheb2 + l * PW;                       // [w][q]

        // A: load [128p x 16w], transpose into As[w][p]
#pragma unroll
        for (int t = 0; t < 2; t++) {
            int idx = tid + t * 256;      // 512 float4s
            int p  = idx >> 2;
            int w4 = (idx & 3) << 2;
            float4 va = *(const float4*)(Aslice + p * LL + w0 + w4);
            As[w4 + 0][p] = va.x;
            As[w4 + 1][p] = va.y;
            As[w4 + 2][p] = va.z;
            As[w4 + 3][p] = va.w;
        }
        // B: direct copy [16w x 128q]
#pragma unroll
        for (int t = 0; t < 2; t++) {
            int idx = tid + t * 256;
            int r = idx >> 5;
            int c4 = (idx & 31) << 2;
            *(float4*)(&Bs[r][c4]) = *(const float4*)(Bslice + (w0 + r) * LL + c4);
        }
        __syncthreads();

#pragma unroll
        for (int hh = 0; hh < 16; hh++) {
            float4 a0 = *(const float4*)(&As[hh][ty * 8]);
            float4 a1 = *(const float4*)(&As[hh][ty * 8 + 4]);
            float4 b0 = *(const float4*)(&Bs[hh][tx * 8]);
            float4 b1 = *(const float4*)(&Bs[hh][tx * 8 + 4]);
            unsigned long long bp[4] = {
                pack2(b0.x, b0.y), pack2(b0.z, b0.w),
                pack2(b1.x, b1.y), pack2(b1.z, b1.w)
            };
            float av[8] = {a0.x, a0.y, a0.z, a0.w, a1.x, a1.y, a1.z, a1.w};
#pragma unroll
            for (int i = 0; i < 8; i++) {
                unsigned long long ap = pack2(av[i], av[i]);
#pragma unroll
                for (int j = 0; j < 4; j++) fma2(acc[i][j], ap, bp[j]);
            }
        }
        __syncthreads();
    }

#pragma unroll
    for (int i = 0; i < 8; i++) {
        float2 p0 = unpack2(acc[i][0]), p1 = unpack2(acc[i][1]);
        float2 p2 = unpack2(acc[i][2]), p3 = unpack2(acc[i][3]);
        float4 o0 = make_float4(p0.x, p0.y, p1.x, p1.y);
        float4 o1 = make_float4(p2.x, p2.y, p3.x, p3.y);
        float* row = Cm + (ty * 8 + i) * LL + tx * 8;
        *(float4*)(row)     = o0;
        *(float4*)(row + 4) = o1;
    }
}

// ============================================================================
extern "C" void kernel_launch(void* const* d_in, const int* in_sizes, int n_in,
                              void* d_out, int out_size)
{
    // Identify inputs by element count (robust to ordering of the two cheb tensors,
    // which contain identical data anyway).
    const float* x = nullptr;
    const float* coefs = nullptr;
    const float* cheb1 = nullptr;
    const float* cheb2 = nullptr;
    for (int i = 0; i < n_in; i++) {
        int sz = in_sizes[i];
        const float* p = (const float*)d_in[i];
        if (sz == BB * CC * PW)          x = p;
        else if (sz == KP * KP * CC * UU) coefs = p;
        else if (sz == KP * PW) {
            if (!cheb1) cheb1 = p; else cheb2 = p;
        }
    }
    if (!cheb2) cheb2 = cheb1;
    float* out = (float*)d_out;

    // Dynamic smem for stage 2 (66.25 KB > 48 KB static limit).
    // cudaFuncSetAttribute is not stream-ordered; legal during graph capture.
    cudaFuncSetAttribute(stage2_kernel,
                         cudaFuncAttributeMaxDynamicSharedMemorySize,
                         S2_SMEM_FLOATS * (int)sizeof(float));

    stage1_kernel<<<BB * CC * KP, 256>>>(x, cheb1);
    stage2_kernel<<<dim3(PW / 128, BB), 256, S2_SMEM_FLOATS * sizeof(float)>>>(coefs);
    stage3_kernel<<<BB * UU, 256>>>(cheb2, out);
}

// round 3
// speedup vs baseline: 1.0602x; 1.0593x over previous
#include <cuda_runtime.h>
#include <cstdint>

#define BB 32
#define CC 16
#define UU 16
#define LL 128
#define PW (LL*LL)
#define KP 5
#define MKC 80
#define MLU 80

// Scratch (zero-init .bss; no runtime allocation)
__device__ float g_t1[BB*KP*CC*PW];
__device__ float g_s [BB*KP*UU*PW];
__device__ float g_c1dup[KP*PW*2];

typedef unsigned long long ull;

__device__ __forceinline__ void fma2(ull& d, ull a, ull b){
  asm("fma.rn.f32x2 %0, %1, %2, %0;" : "+l"(d) : "l"(a), "l"(b));
}
__device__ __forceinline__ float2 unpack2(ull v){
  float2 f; asm("mov.b64 {%0,%1}, %2;" : "=f"(f.x), "=f"(f.y) : "l"(v)); return f;
}
__device__ __forceinline__ void cp16(uint32_t dst, const float* src){
  asm volatile("cp.async.cg.shared.global [%0], [%1], 16;" :: "r"(dst), "l"(src));
}
__device__ __forceinline__ void cp_commit(){ asm volatile("cp.async.commit_group;"); }
template<int N> __device__ __forceinline__ void cp_wait(){
  asm volatile("cp.async.wait_group %0;" :: "n"(N));
}

// ============================================================================
// Prep: g_c1dup[k][h][2p] = g_c1dup[k][h][2p+1] = cheb1[k][h][p]
// ============================================================================
__global__ void dup_kernel(const float* __restrict__ c1){
  int i = blockIdx.x * 256 + threadIdx.x;
  if (i < KP*PW){
    float v = c1[i];
    *(float2*)&g_c1dup[2*i] = make_float2(v, v);
  }
}

// ============================================================================
// Stage 1: t1[b,k,c,p,w] = sum_h cheb1[k,h,p] * x[b,c,h,w]
// A = dup cheb rows [16][256]; B = x rows [16][128]; double-buffered cp.async.
// ============================================================================
#define S1_AB (16*256)
#define S1_BB (16*128)
#define S1_SMEM ((2*S1_AB + 2*S1_BB)*4)   // 49152 B

__global__ __launch_bounds__(256,2) void stage1_kernel(const float* __restrict__ x)
{
  extern __shared__ float sm[];
  float* Asd = sm;                 // [2][16][256]
  float* Bs  = sm + 2*S1_AB;       // [2][16][128]

  int bid = blockIdx.x;
  int k = bid % KP;
  int c = (bid/KP) % CC;
  int b = bid/(KP*CC);
  const float* Adup = g_c1dup + k*(PW*2);
  const float* Bm   = x + (b*CC + c)*PW;
  float* Cm = g_t1 + ((b*KP + k)*CC + c)*PW;

  int tid  = threadIdx.x;
  int lane = tid & 31, warp = tid >> 5;
  int tx = ((warp & 1) << 3) | (lane & 7);   // 0..15 (w groups)
  int ty = ((warp >> 1) << 2) | (lane >> 3); // 0..15 (p groups)

  uint32_t sA = (uint32_t)__cvta_generic_to_shared(Asd);
  uint32_t sB = (uint32_t)__cvta_generic_to_shared(Bs);

  ull acc[8][4];
#pragma unroll
  for (int r = 0; r < 8; r++)
#pragma unroll
    for (int j = 0; j < 4; j++) acc[r][j] = 0ull;

  auto issue = [&](int h0, int buf){
#pragma unroll
    for (int t = 0; t < 4; t++){
      int idx = tid + t*256;                      // 1024 chunks (A)
      int r = idx >> 6, c4 = (idx & 63) << 2;
      cp16(sA + (buf*S1_AB + r*256 + c4)*4, Adup + (h0 + r)*256 + c4);
    }
#pragma unroll
    for (int t = 0; t < 2; t++){
      int idx = tid + t*256;                      // 512 chunks (B)
      int r = idx >> 5, c4 = (idx & 31) << 2;
      cp16(sB + (buf*S1_BB + r*128 + c4)*4, Bm + (h0 + r)*LL + c4);
    }
    cp_commit();
  };

  issue(0, 0);
  int buf = 0;
  for (int kt = 0; kt < 8; kt++){
    cp_wait<0>();
    __syncthreads();
    if (kt < 7) issue((kt+1)*16, buf^1);
    const float* Ab = Asd + buf*S1_AB;
    const float* Bb = Bs  + buf*S1_BB;
#pragma unroll
    for (int hh = 0; hh < 16; hh++){
      const float* ar = Ab + hh*256;
      const float* br = Bb + hh*128;
      ulonglong2 A0 = *(const ulonglong2*)(ar + 8*ty);
      ulonglong2 A1 = *(const ulonglong2*)(ar + 8*ty + 4);
      ulonglong2 A2 = *(const ulonglong2*)(ar + 128 + 8*ty);
      ulonglong2 A3 = *(const ulonglong2*)(ar + 128 + 8*ty + 4);
      ulonglong2 B0 = *(const ulonglong2*)(br + 4*tx);
      ulonglong2 B1 = *(const ulonglong2*)(br + 64 + 4*tx);
      ull ad[8] = {A0.x, A0.y, A1.x, A1.y, A2.x, A2.y, A3.x, A3.y};
      ull bp[4] = {B0.x, B0.y, B1.x, B1.y};
#pragma unroll
      for (int r = 0; r < 8; r++)
#pragma unroll
        for (int j = 0; j < 4; j++) fma2(acc[r][j], ad[r], bp[j]);
    }
    __syncthreads();
    buf ^= 1;
  }

#pragma unroll
  for (int r = 0; r < 8; r++){
    int p = (r < 4) ? (4*ty + r) : (64 + 4*ty + r - 4);
    float2 f0 = unpack2(acc[r][0]), f1 = unpack2(acc[r][1]);
    float2 f2 = unpack2(acc[r][2]), f3 = unpack2(acc[r][3]);
    float* row = Cm + p*LL;
    *(float4*)(row + 4*tx)      = make_float4(f0.x, f0.y, f1.x, f1.y);
    *(float4*)(row + 64 + 4*tx) = make_float4(f2.x, f2.y, f3.x, f3.y);
  }
}

// ============================================================================
// Stage 2: s[b,(l,u),p,w] = sum_{(k,c)} Cmat[(k,c),(l,u)] * t1[b,(k,c),p,w]
// One block per (b, p). Coefs duplicated in smem; pixels paired directly.
// ============================================================================
#define S2_SMEM ((MKC*160 + MKC*128)*4)   // 92160 B

__global__ __launch_bounds__(256,2) void stage2_kernel(const float* __restrict__ coefs)
{
  extern __shared__ float sm[];
  float* Csd = sm;                 // [80][160] duplicated coefs
  float* Ts  = sm + MKC*160;       // [80][128]

  int b    = blockIdx.y;
  int prow = blockIdx.x;           // p index (128 w per row)
  int tid  = threadIdx.x;
  int mg = tid >> 5;               // 8 groups * 10 m
  int tn = tid & 31;               // 32 * 4 w

  uint32_t sT = (uint32_t)__cvta_generic_to_shared(Ts);
  const float* Tb = g_t1 + b*MKC*PW + prow*LL;
#pragma unroll
  for (int t = 0; t < 10; t++){
    int idx = tid + t*256;                       // 2560 chunks
    int r = idx >> 5, c4 = (idx & 31) << 2;
    cp16(sT + (r*128 + c4)*4, Tb + r*PW + c4);
  }
  cp_commit();

  // Build duplicated coef matrix: Csd[kk][2m] = Csd[kk][2m+1] = coefs[k1,l,c,u]
#pragma unroll
  for (int t = 0; t < 25; t++){
    int idx = tid + t*256;                       // 6400
    int kk = idx / MLU;
    int m  = idx % MLU;
    int k1 = kk >> 4, c = kk & 15;
    int l  = m >> 4,  u = m & 15;
    float v = coefs[((k1*KP + l)*CC + c)*UU + u];
    *(float2*)&Csd[kk*160 + 2*m] = make_float2(v, v);
  }
  cp_wait<0>();
  __syncthreads();

  ull acc[10][2];
#pragma unroll
  for (int i = 0; i < 10; i++){ acc[i][0] = 0ull; acc[i][1] = 0ull; }

#pragma unroll 2
  for (int kk = 0; kk < MKC; kk++){
    ulonglong2 bv = *(const ulonglong2*)&Ts[kk*128 + tn*4];
    const float* crow = Csd + kk*160 + 20*mg;
    ulonglong2 c0 = *(const ulonglong2*)(crow);
    ulonglong2 c1 = *(const ulonglong2*)(crow + 4);
    ulonglong2 c2 = *(const ulonglong2*)(crow + 8);
    ulonglong2 c3 = *(const ulonglong2*)(crow + 12);
    ulonglong2 c4 = *(const ulonglong2*)(crow + 16);
    ull cd[10] = {c0.x, c0.y, c1.x, c1.y, c2.x, c2.y, c3.x, c3.y, c4.x, c4.y};
#pragma unroll
    for (int i = 0; i < 10; i++){
      fma2(acc[i][0], cd[i], bv.x);
      fma2(acc[i][1], cd[i], bv.y);
    }
  }

  float* Sb = g_s + b*MLU*PW + prow*LL + tn*4;
#pragma unroll
  for (int i = 0; i < 10; i++){
    float2 f0 = unpack2(acc[i][0]), f1 = unpack2(acc[i][1]);
    *(float4*)(Sb + (mg*10 + i)*PW) = make_float4(f0.x, f0.y, f1.x, f1.y);
  }
}

// ============================================================================
// Stage 3: out[b,u,p,q] = sum_{l,w} s[b,l,u,p,w] * cheb2[l,w,q]
// One block per (b,u). A transposed+duplicated into Asd[w][2p] (stride 260),
// register-staged double buffer; B (cheb2) via cp.async double buffer.
// ============================================================================
#define S3_ASTR 260
#define S3_AB (16*S3_ASTR)
#define S3_BB (16*128)
#define S3_SMEM ((2*S3_AB + 2*S3_BB)*4)   // 49664 B

__global__ __launch_bounds__(256,2) void stage3_kernel(
    const float* __restrict__ cheb2, float* __restrict__ out)
{
  extern __shared__ float sm[];
  float* Asd = sm;                 // [2][16][260]
  float* Bs  = sm + 2*S3_AB;       // [2][16][128]

  int bid = blockIdx.x;
  int u = bid % UU;
  int b = bid / UU;
  float* Cm = out + (b*UU + u)*PW;
  const float* Sbase = g_s + (b*KP*UU + u)*PW;   // + l*UU*PW per l

  int tid  = threadIdx.x;
  int lane = tid & 31, warp = tid >> 5;
  int tx = ((warp & 1) << 3) | (lane & 7);
  int ty = ((warp >> 1) << 2) | (lane >> 3);

  uint32_t sB = (uint32_t)__cvta_generic_to_shared(Bs);

  ull acc[8][4];
#pragma unroll
  for (int r = 0; r < 8; r++)
#pragma unroll
    for (int j = 0; j < 4; j++) acc[r][j] = 0ull;

  int p0 = tid >> 2;                 // 0..63
  int w4 = (tid & 3) << 2;           // 0,4,8,12

  auto issueB = [&](int kt, int buf){
    int l  = kt >> 3;
    int w0 = (kt & 7) << 4;
    const float* Bsl = cheb2 + l*PW + w0*LL;
#pragma unroll
    for (int t = 0; t < 2; t++){
      int idx = tid + t*256;
      int r = idx >> 5, c4 = (idx & 31) << 2;
      cp16(sB + (buf*S3_BB + r*128 + c4)*4, Bsl + r*LL + c4);
    }
    cp_commit();
  };
  auto ldA = [&](int kt, float4* va){
    int l  = kt >> 3;
    int w0 = (kt & 7) << 4;
    const float* Asl = Sbase + l*UU*PW + w0;
    va[0] = *(const float4*)(Asl + p0*LL + w4);
    va[1] = *(const float4*)(Asl + (p0 + 64)*LL + w4);
  };
  auto stsA = [&](const float4* va, int buf){
    float* Ab = Asd + buf*S3_AB;
#pragma unroll
    for (int t = 0; t < 2; t++){
      int p = p0 + t*64;
      float4 v = va[t];
      *(float2*)&Ab[(w4+0)*S3_ASTR + 2*p] = make_float2(v.x, v.x);
      *(float2*)&Ab[(w4+1)*S3_ASTR + 2*p] = make_float2(v.y, v.y);
      *(float2*)&Ab[(w4+2)*S3_ASTR + 2*p] = make_float2(v.z, v.z);
      *(float2*)&Ab[(w4+3)*S3_ASTR + 2*p] = make_float2(v.w, v.w);
    }
  };

  float4 va[2];
  issueB(0, 0);
  ldA(0, va);
  stsA(va, 0);
  cp_wait<0>();
  __syncthreads();

  int buf = 0;
  for (int kt = 0; kt < 40; kt++){
    if (kt < 39){ issueB(kt+1, buf^1); ldA(kt+1, va); }
    const float* Ab = Asd + buf*S3_AB;
    const float* Bb = Bs  + buf*S3_BB;
#pragma unroll
    for (int hh = 0; hh < 16; hh++){
      const float* ar = Ab + hh*S3_ASTR;
      const float* br = Bb + hh*128;
      ulonglong2 A0 = *(const ulonglong2*)(ar + 8*ty);
      ulonglong2 A1 = *(const ulonglong2*)(ar + 8*ty + 4);
      ulonglong2 A2 = *(const ulonglong2*)(ar + 128 + 8*ty);
      ulonglong2 A3 = *(const ulonglong2*)(ar + 128 + 8*ty + 4);
      ulonglong2 B0 = *(const ulonglong2*)(br + 4*tx);
      ulonglong2 B1 = *(const ulonglong2*)(br + 64 + 4*tx);
      ull ad[8] = {A0.x, A0.y, A1.x, A1.y, A2.x, A2.y, A3.x, A3.y};
      ull bp[4] = {B0.x, B0.y, B1.x, B1.y};
#pragma unroll
      for (int r = 0; r < 8; r++)
#pragma unroll
        for (int j = 0; j < 4; j++) fma2(acc[r][j], ad[r], bp[j]);
    }
    if (kt < 39){
      stsA(va, buf^1);
      cp_wait<0>();
    }
    __syncthreads();
    buf ^= 1;
  }

#pragma unroll
  for (int r = 0; r < 8; r++){
    int p = (r < 4) ? (4*ty + r) : (64 + 4*ty + r - 4);
    float2 f0 = unpack2(acc[r][0]), f1 = unpack2(acc[r][1]);
    float2 f2 = unpack2(acc[r][2]), f3 = unpack2(acc[r][3]);
    float* row = Cm + p*LL;
    *(float4*)(row + 4*tx)      = make_float4(f0.x, f0.y, f1.x, f1.y);
    *(float4*)(row + 64 + 4*tx) = make_float4(f2.x, f2.y, f3.x, f3.y);
  }
}

// ============================================================================
extern "C" void kernel_launch(void* const* d_in, const int* in_sizes, int n_in,
                              void* d_out, int out_size)
{
  const float* x = nullptr;
  const float* coefs = nullptr;
  const float* cheb1 = nullptr;
  const float* cheb2 = nullptr;
  for (int i = 0; i < n_in; i++){
    int sz = in_sizes[i];
    const float* p = (const float*)d_in[i];
    if (sz == BB*CC*PW)            x = p;
    else if (sz == KP*KP*CC*UU)    coefs = p;
    else if (sz == KP*PW){ if (!cheb1) cheb1 = p; else cheb2 = p; }
  }
  if (!cheb2) cheb2 = cheb1;
  float* out = (float*)d_out;

  static bool attr_done = false;
  if (!attr_done){
    cudaFuncSetAttribute(stage1_kernel, cudaFuncAttributeMaxDynamicSharedMemorySize, S1_SMEM);
    cudaFuncSetAttribute(stage2_kernel, cudaFuncAttributeMaxDynamicSharedMemorySize, S2_SMEM);
    cudaFuncSetAttribute(stage3_kernel, cudaFuncAttributeMaxDynamicSharedMemorySize, S3_SMEM);
    attr_done = true;
  }

  dup_kernel<<<(KP*PW + 255)/256, 256>>>(cheb1);
  stage1_kernel<<<BB*CC*KP, 256, S1_SMEM>>>(x);
  stage2_kernel<<<dim3(LL, BB), 256, S2_SMEM>>>(coefs);
  stage3_kernel<<<BB*UU, 256, S3_SMEM>>>(cheb2, out);
}

// round 5
// speedup vs baseline: 1.5092x; 1.4235x over previous
#include <cuda_runtime.h>
#include <cuda_bf16.h>
#include <cstdint>

#define BB 32
#define CC 16
#define UU 16
#define LL 128
#define PW (LL*LL)
#define KP 5
#define MKC 80
#define MLU 80

// ------------------------------- scratch ------------------------------------
__device__ float          g_t1 [BB*KP*CC*PW];      // stage1 out (f32)
__device__ __nv_bfloat16  g_Shi[BB*KP*UU*PW];      // stage2 out hi  [b][l*16+u][p][w]
__device__ __nv_bfloat16  g_Slo[BB*KP*UU*PW];      // stage2 out lo
__device__ __nv_bfloat16  g_Xhi[BB*CC*PW];         // x transposed [bc][w][h] hi
__device__ __nv_bfloat16  g_Xlo[BB*CC*PW];
__device__ __nv_bfloat16  g_A1hi[KP*PW];           // cheb1^T [k][p][h]
__device__ __nv_bfloat16  g_A1lo[KP*PW];
__device__ __nv_bfloat16  g_B3hi[KP*PW];           // cheb2^T [l][q][w]
__device__ __nv_bfloat16  g_B3lo[KP*PW];

typedef unsigned long long ull;

// --------------------------- helpers ------------------------------
__device__ __forceinline__ void fma2(ull& d, ull a, ull b){
  asm("fma.rn.f32x2 %0, %1, %2, %0;" : "+l"(d) : "l"(a), "l"(b));
}
__device__ __forceinline__ float2 unpack2(ull v){
  float2 f; asm("mov.b64 {%0,%1}, %2;" : "=f"(f.x), "=f"(f.y) : "l"(v)); return f;
}
__device__ __forceinline__ void cp16(uint32_t dst, const void* src){
  asm volatile("cp.async.cg.shared.global [%0], [%1], 16;" :: "r"(dst), "l"(src));
}
__device__ __forceinline__ void cp_commit(){ asm volatile("cp.async.commit_group;"); }
template<int N> __device__ __forceinline__ void cp_wait(){
  asm volatile("cp.async.wait_group %0;" :: "n"(N));
}
__device__ __forceinline__ uint32_t smem_u32(const void* p){
  return (uint32_t)__cvta_generic_to_shared(p);
}
__device__ __forceinline__ void bsplit(float v, __nv_bfloat16& h, __nv_bfloat16& l){
  h = __float2bfloat16(v);
  l = __float2bfloat16(v - __bfloat162float(h));
}
// m16n8k16 bf16 MMA, fp32 accumulate (sm_80+, no arch-a needed)
__device__ __forceinline__ void mma16816(float* d, const uint32_t* a, const uint32_t* b){
  asm volatile("mma.sync.aligned.m16n8k16.row.col.f32.bf16.bf16.f32 "
    "{%0,%1,%2,%3}, {%4,%5,%6,%7}, {%8,%9}, {%0,%1,%2,%3};"
    : "+f"(d[0]),"+f"(d[1]),"+f"(d[2]),"+f"(d[3])
    : "r"(a[0]),"r"(a[1]),"r"(a[2]),"r"(a[3]), "r"(b[0]),"r"(b[1]));
}
__device__ __forceinline__ void ldsm4(uint32_t* r, uint32_t addr){
  asm volatile("ldmatrix.sync.aligned.m8n8.x4.shared.b16 {%0,%1,%2,%3}, [%4];"
    : "=r"(r[0]),"=r"(r[1]),"=r"(r[2]),"=r"(r[3]) : "r"(addr));
}

// ============================================================================
// Preps
// ============================================================================
__global__ void prep_cheb(const float* __restrict__ c1, const float* __restrict__ c2){
  int i = blockIdx.x*256 + threadIdx.x;
  if (i >= KP*PW) return;
  int k = i / PW, rr = (i % PW) / LL, qq = i % LL;   // src [k][rr][qq]
  int o = k*PW + qq*LL + rr;                          // dst [k][qq][rr]
  __nv_bfloat16 h, l;
  bsplit(c1[i], h, l); g_A1hi[o] = h; g_A1lo[o] = l;
  bsplit(c2[i], h, l); g_B3hi[o] = h; g_B3lo[o] = l;
}

__global__ void prep_x(const float* __restrict__ x){
  __shared__ float t[32][33];
  int bc = blockIdx.z;
  int w0 = blockIdx.x*32, h0 = blockIdx.y*32;
  int tx = threadIdx.x, ty = threadIdx.y;  // 32, 8
  const float* src = x + (size_t)bc*PW;
#pragma unroll
  for (int i = 0; i < 4; i++)
    t[ty + 8*i][tx] = src[(h0 + ty + 8*i)*LL + (w0 + tx)];
  __syncthreads();
  __nv_bfloat16* dh = g_Xhi + (size_t)bc*PW;
  __nv_bfloat16* dl = g_Xlo + (size_t)bc*PW;
#pragma unroll
  for (int i = 0; i < 4; i++){
    int w = w0 + ty + 8*i, h = h0 + tx;
    __nv_bfloat16 hi, lo;
    bsplit(t[tx][ty + 8*i], hi, lo);
    dh[w*LL + h] = hi;
    dl[w*LL + h] = lo;
  }
}

// ============================================================================
// Shared HMMA tile machinery: 128x128 CTA tile, 8 warps (4p x 2n), K16 chunks.
// SMEM chunk = 4 tiles (Ahi,Alo,Bhi,Blo), each [128 rows][24 bf16] (48B rows,
// conflict-free for ldmatrix), 6144 B per tile, double buffered = 49152 B.
// ============================================================================
#define TILE_B   6144
#define BUF_B    (4*TILE_B)
#define GSMEM    (2*BUF_B)

// load one K16 chunk: 4 tiles x 128 rows x 32B = 1024 x 16B chunks, 4/thread
__device__ __forceinline__ void load_chunk(uint32_t sb, int buf,
    const __nv_bfloat16* s0, const __nv_bfloat16* s1,
    const __nv_bfloat16* s2, const __nv_bfloat16* s3, int koff, int tid)
{
  const __nv_bfloat16* srcs[4] = { s0, s1, s2, s3 };
#pragma unroll
  for (int t = 0; t < 4; t++){
    int idx = tid + t*256;
    int tile = idx >> 8, r = (idx >> 1) & 127, half = idx & 1;
    uint32_t d = sb + buf*BUF_B + tile*TILE_B + r*48 + half*16;
    cp16(d, srcs[tile] + r*LL + koff + half*8);
  }
  cp_commit();
}

// compute one K16 chunk: 3-product bf16 split accumulate
__device__ __forceinline__ void compute_chunk(uint32_t sb, int buf,
    float acc[2][8][4], int lane, int p0, int w0)
{
  uint32_t base = sb + buf*BUF_B;
  int lr = lane & 15, lh = lane >> 4;
  uint32_t afr[2][2][4];
#pragma unroll
  for (int var = 0; var < 2; var++)
#pragma unroll
    for (int mt = 0; mt < 2; mt++)
      ldsm4(afr[var][mt], base + var*TILE_B + (p0 + mt*16 + lr)*48 + lh*16);

  int br = (lane & 7) | (((lane >> 4) & 1) << 3);
  int bh = (lane >> 3) & 1;
#pragma unroll
  for (int g = 0; g < 4; g++){
    uint32_t rhi[4], rlo[4];
    ldsm4(rhi, base + 2*TILE_B + (w0 + g*16 + br)*48 + bh*16);
    ldsm4(rlo, base + 3*TILE_B + (w0 + g*16 + br)*48 + bh*16);
#pragma unroll
    for (int sub = 0; sub < 2; sub++){
      int nt = g*2 + sub;
#pragma unroll
      for (int mt = 0; mt < 2; mt++){
        mma16816(acc[mt][nt], afr[0][mt], rhi + sub*2);   // hi*hi
        mma16816(acc[mt][nt], afr[1][mt], rhi + sub*2);   // lo*hi
        mma16816(acc[mt][nt], afr[0][mt], rlo + sub*2);   // hi*lo
      }
    }
  }
}

__device__ __forceinline__ void store_tile(float* D, float acc[2][8][4],
                                           int lane, int p0, int w0)
{
  int q = lane >> 2, qc = (lane & 3)*2;
#pragma unroll
  for (int mt = 0; mt < 2; mt++)
#pragma unroll
    for (int nt = 0; nt < 8; nt++){
      int row = p0 + mt*16 + q, col = w0 + nt*8 + qc;
      *(float2*)(D + (size_t)row*LL + col)       = make_float2(acc[mt][nt][0], acc[mt][nt][1]);
      *(float2*)(D + (size_t)(row+8)*LL + col)   = make_float2(acc[mt][nt][2], acc[mt][nt][3]);
    }
}

// ============================================================================
// Stage 1: per (b,c): for k: D_k[p,w] = sum_h cheb1T[k][p,h] * xT[bc][w,h]
// 40 K16 iters (k = i>>3, h0 = (i&7)*16), epilogue every 8 iters.
// ============================================================================
__global__ __launch_bounds__(256,2) void stage1_mma(){
  extern __shared__ char smem[];
  uint32_t sb = smem_u32(smem);
  int tid = threadIdx.x, wid = tid >> 5, lane = tid & 31;
  int bid = blockIdx.x;
  int c = bid % CC, b = bid / CC;

  const __nv_bfloat16* Xhi = g_Xhi + (size_t)bid*PW;
  const __nv_bfloat16* Xlo = g_Xlo + (size_t)bid*PW;

  int p0 = (wid >> 1)*32, w0 = (wid & 1)*64;

  float acc[2][8][4];
#pragma unroll
  for (int mt = 0; mt < 2; mt++)
#pragma unroll
    for (int nt = 0; nt < 8; nt++)
#pragma unroll
      for (int j = 0; j < 4; j++) acc[mt][nt][j] = 0.f;

  load_chunk(sb, 0, g_A1hi, g_A1lo, Xhi, Xlo, 0, tid);

  for (int i = 0; i < 40; i++){
    int buf = i & 1;
    cp_wait<0>();
    __syncthreads();
    if (i < 39){
      int kn = (i+1) >> 3, hn = ((i+1) & 7) << 4;
      load_chunk(sb, buf^1, g_A1hi + (size_t)kn*PW, g_A1lo + (size_t)kn*PW,
                 Xhi, Xlo, hn, tid);
    }
    compute_chunk(sb, buf, acc, lane, p0, w0);
    if ((i & 7) == 7){
      int k = i >> 3;
      float* D = g_t1 + ((size_t)(b*KP + k)*CC + c)*PW;
      store_tile(D, acc, lane, p0, w0);
#pragma unroll
      for (int mt = 0; mt < 2; mt++)
#pragma unroll
        for (int nt = 0; nt < 8; nt++)
#pragma unroll
          for (int j = 0; j < 4; j++) acc[mt][nt][j] = 0.f;
    }
  }
}

// ============================================================================
// Stage 2 (FFMA2): s[b,(l,u),p,w] = sum_{(k,c)} Cmat * t1 ; outputs bf16 hi/lo
// ============================================================================
#define S2_SMEM ((MKC*160 + MKC*128)*4)   // 92160 B

__global__ __launch_bounds__(256,2) void stage2_kernel(const float* __restrict__ coefs)
{
  extern __shared__ float sm[];
  float* Csd = sm;                 // [80][160] duplicated coefs
  float* Ts  = sm + MKC*160;       // [80][128]

  int b    = blockIdx.y;
  int prow = blockIdx.x;
  int tid  = threadIdx.x;
  int mg = tid >> 5;
  int tn = tid & 31;

  uint32_t sT = smem_u32(Ts);
  const float* Tb = g_t1 + (size_t)b*MKC*PW + prow*LL;
#pragma unroll
  for (int t = 0; t < 10; t++){
    int idx = tid + t*256;
    int r = idx >> 5, c4 = (idx & 31) << 2;
    cp16(sT + (r*128 + c4)*4, Tb + (size_t)r*PW + c4);
  }
  cp_commit();

#pragma unroll
  for (int t = 0; t < 25; t++){
    int idx = tid + t*256;
    int kk = idx / MLU;
    int m  = idx % MLU;
    int k1 = kk >> 4, c = kk & 15;
    int l  = m >> 4,  u = m & 15;
    float v = coefs[((k1*KP + l)*CC + c)*UU + u];
    *(float2*)&Csd[kk*160 + 2*m] = make_float2(v, v);
  }
  cp_wait<0>();
  __syncthreads();

  ull acc[10][2];
#pragma unroll
  for (int i = 0; i < 10; i++){ acc[i][0] = 0ull; acc[i][1] = 0ull; }

#pragma unroll 2
  for (int kk = 0; kk < MKC; kk++){
    ulonglong2 bv = *(const ulonglong2*)&Ts[kk*128 + tn*4];
    const float* crow = Csd + kk*160 + 20*mg;
    ulonglong2 c0 = *(const ulonglong2*)(crow);
    ulonglong2 c1 = *(const ulonglong2*)(crow + 4);
    ulonglong2 c2 = *(const ulonglong2*)(crow + 8);
    ulonglong2 c3 = *(const ulonglong2*)(crow + 12);
    ulonglong2 c4 = *(const ulonglong2*)(crow + 16);
    ull cd[10] = {c0.x, c0.y, c1.x, c1.y, c2.x, c2.y, c3.x, c3.y, c4.x, c4.y};
#pragma unroll
    for (int i = 0; i < 10; i++){
      fma2(acc[i][0], cd[i], bv.x);
      fma2(acc[i][1], cd[i], bv.y);
    }
  }

#pragma unroll
  for (int i = 0; i < 10; i++){
    float2 f0 = unpack2(acc[i][0]), f1 = unpack2(acc[i][1]);
    float v[4] = {f0.x, f0.y, f1.x, f1.y};
    uint32_t hs[4], ls[4];
#pragma unroll
    for (int j = 0; j < 4; j++){
      __nv_bfloat16 h, l;
      bsplit(v[j], h, l);
      hs[j] = (uint32_t)__bfloat16_as_ushort(h);
      ls[j] = (uint32_t)__bfloat16_as_ushort(l);
    }
    uint2 hv = make_uint2(hs[0] | (hs[1]<<16), hs[2] | (hs[3]<<16));
    uint2 lv = make_uint2(ls[0] | (ls[1]<<16), ls[2] | (ls[3]<<16));
    size_t off = (size_t)(b*MLU + mg*10 + i)*PW + prow*LL + tn*4;
    *(uint2*)&g_Shi[off] = hv;
    *(uint2*)&g_Slo[off] = lv;
  }
}

// ============================================================================
// Stage 3: per (b,u): D[p,q] = sum_{l,w} s[b,l,u][p,w] * cheb2T[l][q,w]
// 40 K16 iters (l = i>>3, w0 = (i&7)*16), single epilogue.
// ============================================================================
__global__ __launch_bounds__(256,2) void stage3_mma(float* __restrict__ out){
  extern __shared__ char smem[];
  uint32_t sb = smem_u32(smem);
  int tid = threadIdx.x, wid = tid >> 5, lane = tid & 31;
  int bid = blockIdx.x;
  int u = bid % UU, b = bid / UU;

  int p0 = (wid >> 1)*32, w0 = (wid & 1)*64;

  float acc[2][8][4];
#pragma unroll
  for (int mt = 0; mt < 2; mt++)
#pragma unroll
    for (int nt = 0; nt < 8; nt++)
#pragma unroll
      for (int j = 0; j < 4; j++) acc[mt][nt][j] = 0.f;

  auto srcA = [&](int l){ return (size_t)(b*MLU + l*UU + u)*PW; };

  load_chunk(sb, 0, g_Shi + srcA(0), g_Slo + srcA(0), g_B3hi, g_B3lo, 0, tid);

  for (int i = 0; i < 40; i++){
    int buf = i & 1;
    cp_wait<0>();
    __syncthreads();
    if (i < 39){
      int ln = (i+1) >> 3, wn = ((i+1) & 7) << 4;
      load_chunk(sb, buf^1, g_Shi + srcA(ln), g_Slo + srcA(ln),
                 g_B3hi + (size_t)ln*PW, g_B3lo + (size_t)ln*PW, wn, tid);
    }
    compute_chunk(sb, buf, acc, lane, p0, w0);
  }

  float* D = out + (size_t)(b*UU + u)*PW;
  store_tile(D, acc, lane, p0, w0);
}

// ============================================================================
extern "C" void kernel_launch(void* const* d_in, const int* in_sizes, int n_in,
                              void* d_out, int out_size)
{
  const float* x = nullptr;
  const float* coefs = nullptr;
  const float* cheb1 = nullptr;
  const float* cheb2 = nullptr;
  for (int i = 0; i < n_in; i++){
    int sz = in_sizes[i];
    const float* p = (const float*)d_in[i];
    if (sz == BB*CC*PW)            x = p;
    else if (sz == KP*KP*CC*UU)    coefs = p;
    else if (sz == KP*PW){ if (!cheb1) cheb1 = p; else cheb2 = p; }
  }
  if (!cheb2) cheb2 = cheb1;
  float* out = (float*)d_out;

  cudaFuncSetAttribute(stage1_mma,    cudaFuncAttributeMaxDynamicSharedMemorySize, GSMEM);
  cudaFuncSetAttribute(stage2_kernel, cudaFuncAttributeMaxDynamicSharedMemorySize, S2_SMEM);
  cudaFuncSetAttribute(stage3_mma,    cudaFuncAttributeMaxDynamicSharedMemorySize, GSMEM);

  prep_cheb<<<(KP*PW + 255)/256, 256>>>(cheb1, cheb2);
  prep_x<<<dim3(4,4,BB*CC), dim3(32,8)>>>(x);
  stage1_mma<<<BB*CC, 256, GSMEM>>>();
  stage2_kernel<<<dim3(LL, BB), 256, S2_SMEM>>>(coefs);
  stage3_mma<<<BB*UU, 256, GSMEM>>>(out);
}

// round 6
// speedup vs baseline: 3.8663x; 2.5619x over previous
#include <cuda_runtime.h>
#include <cuda_bf16.h>
#include <cstdint>

#define BB 32
#define CC 16
#define UU 16
#define LL 128
#define PW (LL*LL)
#define KP 5
#define MKC 80
#define MLU 80

// ------------------------------- scratch ------------------------------------
__device__ __nv_bfloat16 g_T1hi[BB*KP*CC*PW];   // t1 split hi [b][kk][pix]
__device__ __nv_bfloat16 g_T1lo[BB*KP*CC*PW];
__device__ float         g_band1[LL*25];        // packed band of cheb1 [p][25]
__device__ float         g_band2[LL*25];        // packed band of cheb2 [q][25]
__device__ __nv_bfloat16 g_Chi[MLU*88];         // coef matrix split [m][kk pad 88]
__device__ __nv_bfloat16 g_Clo[MLU*88];

// --------------------------- helpers ------------------------------
__device__ __forceinline__ void cp16(uint32_t dst, const void* src){
  asm volatile("cp.async.cg.shared.global [%0], [%1], 16;" :: "r"(dst), "l"(src));
}
__device__ __forceinline__ void cp4(uint32_t dst, const void* src){
  asm volatile("cp.async.ca.shared.global [%0], [%1], 4;" :: "r"(dst), "l"(src));
}
__device__ __forceinline__ void cp_commit(){ asm volatile("cp.async.commit_group;"); }
template<int N> __device__ __forceinline__ void cp_wait(){
  asm volatile("cp.async.wait_group %0;" :: "n"(N));
}
__device__ __forceinline__ uint32_t smem_u32(const void* p){
  return (uint32_t)__cvta_generic_to_shared(p);
}
__device__ __forceinline__ void bsplit(float v, __nv_bfloat16& h, __nv_bfloat16& l){
  h = __float2bfloat16(v);
  l = __float2bfloat16(v - __bfloat162float(h));
}
__device__ __forceinline__ void mma16816(float* d, const uint32_t* a, const uint32_t* b){
  asm volatile("mma.sync.aligned.m16n8k16.row.col.f32.bf16.bf16.f32 "
    "{%0,%1,%2,%3}, {%4,%5,%6,%7}, {%8,%9}, {%0,%1,%2,%3};"
    : "+f"(d[0]),"+f"(d[1]),"+f"(d[2]),"+f"(d[3])
    : "r"(a[0]),"r"(a[1]),"r"(a[2]),"r"(a[3]), "r"(b[0]),"r"(b[1]));
}
__device__ __forceinline__ void ldsm4(uint32_t* r, uint32_t addr){
  asm volatile("ldmatrix.sync.aligned.m8n8.x4.shared.b16 {%0,%1,%2,%3}, [%4];"
    : "=r"(r[0]),"=r"(r[1]),"=r"(r[2]),"=r"(r[3]) : "r"(addr));
}
__device__ __forceinline__ void ldsm4t(uint32_t* r, uint32_t addr){
  asm volatile("ldmatrix.sync.aligned.m8n8.x4.trans.shared.b16 {%0,%1,%2,%3}, [%4];"
    : "=r"(r[0]),"=r"(r[1]),"=r"(r[2]),"=r"(r[3]) : "r"(addr));
}

// ============================================================================
// Prep: band tables (T_k has bandwidth k — exact structural zeros) + coef split
// band[p][k*k + k + d] = cheb[k][p+d][p] for d in [-k,k] (0 if out of image)
// ============================================================================
__global__ void prep_tabs(const float* __restrict__ c1, const float* __restrict__ c2,
                          const float* __restrict__ coefs){
  int t = threadIdx.x;   // 256 threads, single block
  if (t < LL){
    for (int k = 0; k < KP; k++)
      for (int d = -k; d <= k; d++){
        int h = t + d;
        bool ok = (h >= 0 && h < LL);
        g_band1[t*25 + k*k + k + d] = ok ? c1[(k*LL + h)*LL + t] : 0.f;
        g_band2[t*25 + k*k + k + d] = ok ? c2[(k*LL + h)*LL + t] : 0.f;
      }
  }
  for (int i = t; i < MLU*88; i += 256){
    int m = i / 88, kk = i % 88;
    float v = 0.f;
    if (kk < MKC){
      int l = m >> 4, u = m & 15, k1 = kk >> 4, c = kk & 15;
      v = coefs[((k1*KP + l)*CC + c)*UU + u];
    }
    __nv_bfloat16 h, l2;
    bsplit(v, h, l2);
    g_Chi[i] = h;
    g_Clo[i] = l2;
  }
}

// ============================================================================
// Stage 1 (exact fp32 stencil): t1[b,k,c,p,w] = sum_{d=-k..k} band1[p][..]*x[b,c,p+d,w]
// Output split to bf16 hi/lo. Grid (8 p-tiles, 512 bc), 128 threads.
// ============================================================================
__global__ __launch_bounds__(128) void stage1_stencil(const float* __restrict__ x){
  __shared__ float bnd[16*25];
  int bc = blockIdx.y;
  int b = bc >> 4, c = bc & 15;
  int pt = blockIdx.x;
  int tid = threadIdx.x;

  for (int i = tid; i < 16*25; i += 128) bnd[i] = g_band1[(pt*16)*25 + i];
  __syncthreads();

  int psub = tid >> 5;            // 0..3, each handles 4 p's
  int w4   = (tid & 31) << 2;     // float4 column
  const float* xs = x + (size_t)bc*PW;
  int pbase = pt*16 + psub*4;

  float4 win[12];
#pragma unroll
  for (int r = 0; r < 12; r++){
    int h = pbase - 4 + r;
    h = h < 0 ? 0 : (h > 127 ? 127 : h);
    win[r] = *(const float4*)(xs + h*LL + w4);
  }

#pragma unroll
  for (int j = 0; j < 4; j++){
    int p = pbase + j;
    const float* bp = bnd + (psub*4 + j)*25;
#pragma unroll
    for (int k = 0; k < KP; k++){
      float4 o = make_float4(0.f, 0.f, 0.f, 0.f);
#pragma unroll
      for (int d = -k; d <= k; d++){
        float cf = bp[k*k + k + d];
        float4 v = win[4 + j + d];
        o.x = fmaf(cf, v.x, o.x);
        o.y = fmaf(cf, v.y, o.y);
        o.z = fmaf(cf, v.z, o.z);
        o.w = fmaf(cf, v.w, o.w);
      }
      // split and store 4 hi + 4 lo bf16
      __nv_bfloat16 h0,l0,h1,l1,h2,l2,h3,l3;
      bsplit(o.x,h0,l0); bsplit(o.y,h1,l1); bsplit(o.z,h2,l2); bsplit(o.w,h3,l3);
      uint2 hv = make_uint2((uint32_t)__bfloat16_as_ushort(h0) | ((uint32_t)__bfloat16_as_ushort(h1)<<16),
                            (uint32_t)__bfloat16_as_ushort(h2) | ((uint32_t)__bfloat16_as_ushort(h3)<<16));
      uint2 lv = make_uint2((uint32_t)__bfloat16_as_ushort(l0) | ((uint32_t)__bfloat16_as_ushort(l1)<<16),
                            (uint32_t)__bfloat16_as_ushort(l2) | ((uint32_t)__bfloat16_as_ushort(l3)<<16));
      size_t base = (size_t)(b*MKC + k*CC + c)*PW + p*LL + w4;
      *(uint2*)&g_T1hi[base] = hv;
      *(uint2*)&g_T1lo[base] = lv;
    }
  }
}

// ============================================================================
// Fused stage 2+3: per (b, p-row):
//   HMMA: s[m=(l,u)][w] = sum_kk C[m][kk] * t1[b][kk][p][w]   (3-product bf16)
//   then stencil: out[b,u,p,q] = sum_l sum_d band2[q][..] * s[l*16+u][q+d]
// SMEM: t1hi [80][136]bf16 | t1lo | Chi [80][88]bf16 | Clo | s [80][132]f32
// band2 (12.8KB) overlaid into t1hi region after MMA phase.
// ============================================================================
#define F_T1H 0
#define F_T1L 21760
#define F_CH  43520
#define F_CL  57600
#define F_S   71680
#define F_SMEM 113920   // bytes

__global__ __launch_bounds__(320,2) void fused_s23(float* __restrict__ out){
  extern __shared__ char smem[];
  uint32_t sb = smem_u32(smem);
  int tid = threadIdx.x, wid = tid >> 5, lane = tid & 31;
  int p = blockIdx.x, b = blockIdx.y;

  // ---- loads: C split (1760 chunks) + t1 tile (2560 chunks) ----
  for (int i = tid; i < 1760; i += 320){
    int var = (i >= 880);
    int j = i - var*880;
    int r = j / 11, ch = j % 11;
    const __nv_bfloat16* src = (var ? g_Clo : g_Chi) + r*88 + ch*8;
    cp16(sb + (var ? F_CL : F_CH) + r*176 + ch*16, src);
  }
  {
    const __nv_bfloat16* th = g_T1hi + (size_t)b*MKC*PW + p*LL;
    const __nv_bfloat16* tl = g_T1lo + (size_t)b*MKC*PW + p*LL;
    for (int i = tid; i < 2560; i += 320){
      int var = (i >= 1280);
      int j = i - var*1280;
      int r = j >> 4, ch = j & 15;
      const __nv_bfloat16* src = (var ? tl : th) + (size_t)r*PW + ch*8;
      cp16(sb + (var ? F_T1L : F_T1H) + r*272 + ch*16, src);
    }
  }
  cp_commit();
  cp_wait<0>();
  __syncthreads();

  // ---- HMMA: 10 warps = 5 m-tiles x 2 n-halves; warp tile 16m x 64w ----
  int mi = wid >> 1, ni = wid & 1;
  float acc[8][4];
#pragma unroll
  for (int nt = 0; nt < 8; nt++)
#pragma unroll
    for (int j = 0; j < 4; j++) acc[nt][j] = 0.f;

  uint32_t arow = (uint32_t)(mi*16 + (lane & 15));
  uint32_t alh  = (uint32_t)((lane >> 4) * 16);
  uint32_t brow16 = (uint32_t)(lane & 15);
  uint32_t blh  = (uint32_t)((lane >> 4) * 16);

#pragma unroll
  for (int kt = 0; kt < 5; kt++){
    uint32_t a_h[4], a_l[4];
    uint32_t aaddr = arow*176 + (uint32_t)kt*32 + alh;
    ldsm4(a_h, sb + F_CH + aaddr);
    ldsm4(a_l, sb + F_CL + aaddr);
#pragma unroll
    for (int g = 0; g < 4; g++){
      uint32_t b_h[4], b_l[4];
      uint32_t baddr = ((uint32_t)kt*16 + brow16)*272 + (uint32_t)(ni*128 + g*32) + blh;
      ldsm4t(b_h, sb + F_T1H + baddr);
      ldsm4t(b_l, sb + F_T1L + baddr);
#pragma unroll
      for (int sub = 0; sub < 2; sub++){
        mma16816(acc[g*2+sub], a_h, b_h + sub*2);
        mma16816(acc[g*2+sub], a_h, b_l + sub*2);
        mma16816(acc[g*2+sub], a_l, b_h + sub*2);
      }
    }
  }

  __syncthreads();   // all warps done reading t1 tiles before band2 overlay

  // band2 table into dead t1hi region (async, overlapped with s-tile writes)
  for (int i = tid; i < LL*25; i += 320)
    cp4(sb + F_T1H + i*4, g_band2 + i);
  cp_commit();

  // accumulators -> s tile [80][132] f32
  {
    float* sT = (float*)(smem + F_S);
    int gid = lane >> 2, qc = (lane & 3)*2;
    int row = mi*16 + gid;
#pragma unroll
    for (int nt = 0; nt < 8; nt++){
      int col = ni*64 + nt*8 + qc;
      sT[row*132 + col]       = acc[nt][0];
      sT[row*132 + col + 1]   = acc[nt][1];
      sT[(row+8)*132 + col]   = acc[nt][2];
      sT[(row+8)*132 + col+1] = acc[nt][3];
    }
  }
  cp_wait<0>();
  __syncthreads();

  // ---- stage-3 stencil: out[b,u,p,q] = sum_l sum_d band2[q]*s[l*16+u][q+d] ----
  {
    const float* bnd = (const float*)(smem + F_T1H);
    const float* sT  = (const float*)(smem + F_S);
    for (int i = tid; i < UU*LL; i += 320){
      int u = i >> 7, q = i & 127;
      const float* bq = bnd + q*25;
      float o = 0.f;
#pragma unroll
      for (int l = 0; l < KP; l++){
        const float* srow = sT + (l*UU + u)*132;
#pragma unroll
        for (int d = -l; d <= l; d++){
          int w = q + d;
          w = w < 0 ? 0 : (w > 127 ? 127 : w);   // coef is 0 when out of image
          o = fmaf(bq[l*l + l + d], srow[w], o);
        }
      }
      out[((size_t)(b*UU + u)*LL + p)*LL + q] = o;
    }
  }
}

// ============================================================================
extern "C" void kernel_launch(void* const* d_in, const int* in_sizes, int n_in,
                              void* d_out, int out_size)
{
  const float* x = nullptr;
  const float* coefs = nullptr;
  const float* cheb1 = nullptr;
  const float* cheb2 = nullptr;
  for (int i = 0; i < n_in; i++){
    int sz = in_sizes[i];
    const float* p = (const float*)d_in[i];
    if (sz == BB*CC*PW)            x = p;
    else if (sz == KP*KP*CC*UU)    coefs = p;
    else if (sz == KP*PW){ if (!cheb1) cheb1 = p; else cheb2 = p; }
  }
  if (!cheb2) cheb2 = cheb1;
  float* out = (float*)d_out;

  cudaFuncSetAttribute(fused_s23, cudaFuncAttributeMaxDynamicSharedMemorySize, F_SMEM);

  prep_tabs<<<1, 256>>>(cheb1, cheb2, coefs);
  stage1_stencil<<<dim3(8, 512), 128>>>(x);
  fused_s23<<<dim3(LL, BB), 320, F_SMEM>>>(out);
}

// round 7
// speedup vs baseline: 4.6534x; 1.2036x over previous
#include <cuda_runtime.h>
#include <cuda_bf16.h>
#include <cstdint>

#define BB 32
#define CC 16
#define UU 16
#define LL 128
#define PW (LL*LL)
#define KP 5
#define MKC 80
#define MLU 80

// ------------------------------- scratch ------------------------------------
__device__ float         g_band1[LL*25];        // packed band of cheb1 [p][25]
__device__ float         g_band2[LL*25];        // packed band of cheb2 [q][25]
__device__ __nv_bfloat16 g_Chi[MLU*88];         // coef matrix split [m][kk pad 88]
__device__ __nv_bfloat16 g_Clo[MLU*88];

// --------------------------- helpers ------------------------------
__device__ __forceinline__ void cp16(uint32_t dst, const void* src){
  asm volatile("cp.async.cg.shared.global [%0], [%1], 16;" :: "r"(dst), "l"(src));
}
__device__ __forceinline__ void cp4(uint32_t dst, const void* src){
  asm volatile("cp.async.ca.shared.global [%0], [%1], 4;" :: "r"(dst), "l"(src));
}
__device__ __forceinline__ void cp_commit(){ asm volatile("cp.async.commit_group;"); }
template<int N> __device__ __forceinline__ void cp_wait(){
  asm volatile("cp.async.wait_group %0;" :: "n"(N));
}
__device__ __forceinline__ uint32_t smem_u32(const void* p){
  return (uint32_t)__cvta_generic_to_shared(p);
}
__device__ __forceinline__ void bsplit(float v, __nv_bfloat16& h, __nv_bfloat16& l){
  h = __float2bfloat16(v);
  l = __float2bfloat16(v - __bfloat162float(h));
}
__device__ __forceinline__ void mma16816(float* d, const uint32_t* a, const uint32_t* b){
  asm volatile("mma.sync.aligned.m16n8k16.row.col.f32.bf16.bf16.f32 "
    "{%0,%1,%2,%3}, {%4,%5,%6,%7}, {%8,%9}, {%0,%1,%2,%3};"
    : "+f"(d[0]),"+f"(d[1]),"+f"(d[2]),"+f"(d[3])
    : "r"(a[0]),"r"(a[1]),"r"(a[2]),"r"(a[3]), "r"(b[0]),"r"(b[1]));
}
__device__ __forceinline__ void ldsm4(uint32_t* r, uint32_t addr){
  asm volatile("ldmatrix.sync.aligned.m8n8.x4.shared.b16 {%0,%1,%2,%3}, [%4];"
    : "=r"(r[0]),"=r"(r[1]),"=r"(r[2]),"=r"(r[3]) : "r"(addr));
}
__device__ __forceinline__ void ldsm4t(uint32_t* r, uint32_t addr){
  asm volatile("ldmatrix.sync.aligned.m8n8.x4.trans.shared.b16 {%0,%1,%2,%3}, [%4];"
    : "=r"(r[0]),"=r"(r[1]),"=r"(r[2]),"=r"(r[3]) : "r"(addr));
}

// ============================================================================
// Prep (parallel): band tables (T_k has bandwidth k — exact structural zeros)
// band[p][k*k + k + d] = cheb[k][p+d][p], d in [-k,k] (0 outside image);
// plus split coef matrix C[m=(l,u)][kk=(k1,c)] -> bf16 hi/lo, kk padded to 88.
// ============================================================================
__global__ void prep_tabs(const float* __restrict__ c1, const float* __restrict__ c2,
                          const float* __restrict__ coefs){
  int gt = blockIdx.x*128 + threadIdx.x;   // 64 blocks x 128 threads = 8192
  if (gt < LL){
    int t = gt;
#pragma unroll
    for (int k = 0; k < KP; k++)
      for (int d = -k; d <= k; d++){
        int h = t + d;
        bool ok = (h >= 0 && h < LL);
        g_band1[t*25 + k*k + k + d] = ok ? c1[(k*LL + h)*LL + t] : 0.f;
        g_band2[t*25 + k*k + k + d] = ok ? c2[(k*LL + h)*LL + t] : 0.f;
      }
  }
  for (int i = gt; i < MLU*88; i += 8192){
    int m = i / 88, kk = i % 88;
    float v = 0.f;
    if (kk < MKC){
      int l = m >> 4, u = m & 15, k1 = kk >> 4, c = kk & 15;
      v = coefs[((k1*KP + l)*CC + c)*UU + u];
    }
    __nv_bfloat16 h, l2;
    bsplit(v, h, l2);
    g_Chi[i] = h;
    g_Clo[i] = l2;
  }
}

// ============================================================================
// Fully fused kernel, one block per (b, p):
//   phase A (stencil, exact fp32): t1[kk=(k,c)][w] = sum_d band1[p][k,d]*x[b,c,p+d,w]
//            -> split bf16 hi/lo straight into ldsm-format smem tiles
//   phase B (HMMA, 3-product bf16): s[m=(l,u)][w] = sum_kk C[m][kk]*t1[kk][w]
//   phase C (stencil, fp32): out[b,u,p,q] = sum_l sum_d band2[q][l,d]*s[l*16+u][q+d]
// SMEM: t1hi [80][136]bf16 | t1lo | Chi [80][88]bf16 | Clo | s [80][132]f32
// band2 (12.8KB) overlaid into dead t1hi region after MMA. 113920 B, occ 2.
// ============================================================================
#define F_T1H 0
#define F_T1L 21760
#define F_CH  43520
#define F_CL  57600
#define F_S   71680
#define F_SMEM 113920   // bytes

__global__ __launch_bounds__(320,2) void fused_all(const float* __restrict__ x,
                                                   float* __restrict__ out){
  extern __shared__ char smem[];
  uint32_t sb = smem_u32(smem);
  int tid = threadIdx.x, wid = tid >> 5, lane = tid & 31;
  int p = blockIdx.x, b = blockIdx.y;

  // ---- async C-tile loads (overlap with stencil below) ----
  for (int i = tid; i < 1760; i += 320){
    int var = (i >= 880);
    int j = i - var*880;
    int r = j / 11, ch = j % 11;
    const __nv_bfloat16* src = (var ? g_Clo : g_Chi) + r*88 + ch*8;
    cp16(sb + (var ? F_CL : F_CH) + r*176 + ch*16, src);
  }
  cp_commit();

  // ---- band1[p] broadcast into registers ----
  float bnd[25];
#pragma unroll
  for (int j = 0; j < 25; j++) bnd[j] = g_band1[p*25 + j];

  // ---- phase A: stage-1 stencil, registers -> split bf16 smem tiles ----
  // 512 tasks = 16 c x 32 w-quads; each loads 9 clamped x rows (float4)
  for (int i = tid; i < 512; i += 320){
    int c  = i >> 5;
    int w4 = (i & 31) << 2;
    const float* xs = x + (size_t)(b*CC + c)*PW + w4;
    float4 win[9];
#pragma unroll
    for (int r = 0; r < 9; r++){
      int h = p - 4 + r;
      h = h < 0 ? 0 : (h > 127 ? 127 : h);
      win[r] = *(const float4*)(xs + h*LL);
    }
#pragma unroll
    for (int k = 0; k < KP; k++){
      float4 o = make_float4(0.f, 0.f, 0.f, 0.f);
#pragma unroll
      for (int d = -k; d <= k; d++){
        float cf = bnd[k*k + k + d];
        float4 v = win[4 + d];
        o.x = fmaf(cf, v.x, o.x);
        o.y = fmaf(cf, v.y, o.y);
        o.z = fmaf(cf, v.z, o.z);
        o.w = fmaf(cf, v.w, o.w);
      }
      __nv_bfloat16 h0,l0,h1,l1,h2,l2,h3,l3;
      bsplit(o.x,h0,l0); bsplit(o.y,h1,l1); bsplit(o.z,h2,l2); bsplit(o.w,h3,l3);
      uint2 hv = make_uint2((uint32_t)__bfloat16_as_ushort(h0) | ((uint32_t)__bfloat16_as_ushort(h1)<<16),
                            (uint32_t)__bfloat16_as_ushort(h2) | ((uint32_t)__bfloat16_as_ushort(h3)<<16));
      uint2 lv = make_uint2((uint32_t)__bfloat16_as_ushort(l0) | ((uint32_t)__bfloat16_as_ushort(l1)<<16),
                            (uint32_t)__bfloat16_as_ushort(l2) | ((uint32_t)__bfloat16_as_ushort(l3)<<16));
      uint32_t off = (uint32_t)((k*CC + c)*272 + w4*2);
      *(uint2*)(smem + F_T1H + off) = hv;
      *(uint2*)(smem + F_T1L + off) = lv;
    }
  }

  cp_wait<0>();
  __syncthreads();

  // ---- phase B: HMMA, 10 warps = 5 m-tiles x 2 n-halves, warp tile 16m x 64w
  int mi = wid >> 1, ni = wid & 1;
  float acc[8][4];
#pragma unroll
  for (int nt = 0; nt < 8; nt++)
#pragma unroll
    for (int j = 0; j < 4; j++) acc[nt][j] = 0.f;

  uint32_t arow = (uint32_t)(mi*16 + (lane & 15));
  uint32_t alh  = (uint32_t)((lane >> 4) * 16);
  uint32_t brow16 = (uint32_t)(lane & 15);
  uint32_t blh  = (uint32_t)((lane >> 4) * 16);

#pragma unroll
  for (int kt = 0; kt < 5; kt++){
    uint32_t a_h[4], a_l[4];
    uint32_t aaddr = arow*176 + (uint32_t)kt*32 + alh;
    ldsm4(a_h, sb + F_CH + aaddr);
    ldsm4(a_l, sb + F_CL + aaddr);
#pragma unroll
    for (int g = 0; g < 4; g++){
      uint32_t b_h[4], b_l[4];
      uint32_t baddr = ((uint32_t)kt*16 + brow16)*272 + (uint32_t)(ni*128 + g*32) + blh;
      ldsm4t(b_h, sb + F_T1H + baddr);
      ldsm4t(b_l, sb + F_T1L + baddr);
#pragma unroll
      for (int sub = 0; sub < 2; sub++){
        mma16816(acc[g*2+sub], a_h, b_h + sub*2);
        mma16816(acc[g*2+sub], a_h, b_l + sub*2);
        mma16816(acc[g*2+sub], a_l, b_h + sub*2);
      }
    }
  }

  __syncthreads();   // all warps done reading t1 tiles before band2 overlay

  // band2 table into dead t1hi region (async, overlapped with s-tile writes)
  for (int i = tid; i < LL*25; i += 320)
    cp4(sb + F_T1H + i*4, g_band2 + i);
  cp_commit();

  // accumulators -> s tile [80][132] f32
  {
    float* sT = (float*)(smem + F_S);
    int gid = lane >> 2, qc = (lane & 3)*2;
    int row = mi*16 + gid;
#pragma unroll
    for (int nt = 0; nt < 8; nt++){
      int col = ni*64 + nt*8 + qc;
      sT[row*132 + col]       = acc[nt][0];
      sT[row*132 + col + 1]   = acc[nt][1];
      sT[(row+8)*132 + col]   = acc[nt][2];
      sT[(row+8)*132 + col+1] = acc[nt][3];
    }
  }
  cp_wait<0>();
  __syncthreads();

  // ---- phase C: stage-3 stencil ----
  {
    const float* bq_all = (const float*)(smem + F_T1H);
    const float* sT  = (const float*)(smem + F_S);
    for (int i = tid; i < UU*LL; i += 320){
      int u = i >> 7, q = i & 127;
      const float* bq = bq_all + q*25;
      float o = 0.f;
#pragma unroll
      for (int l = 0; l < KP; l++){
        const float* srow = sT + (l*UU + u)*132;
#pragma unroll
        for (int d = -l; d <= l; d++){
          int w = q + d;
          w = w < 0 ? 0 : (w > 127 ? 127 : w);   // coef is 0 when out of image
          o = fmaf(bq[l*l + l + d], srow[w], o);
        }
      }
      out[((size_t)(b*UU + u)*LL + p)*LL + q] = o;
    }
  }
}

// ============================================================================
extern "C" void kernel_launch(void* const* d_in, const int* in_sizes, int n_in,
                              void* d_out, int out_size)
{
  const float* x = nullptr;
  const float* coefs = nullptr;
  const float* cheb1 = nullptr;
  const float* cheb2 = nullptr;
  for (int i = 0; i < n_in; i++){
    int sz = in_sizes[i];
    const float* p = (const float*)d_in[i];
    if (sz == BB*CC*PW)            x = p;
    else if (sz == KP*KP*CC*UU)    coefs = p;
    else if (sz == KP*PW){ if (!cheb1) cheb1 = p; else cheb2 = p; }
  }
  if (!cheb2) cheb2 = cheb1;
  float* out = (float*)d_out;

  cudaFuncSetAttribute(fused_all, cudaFuncAttributeMaxDynamicSharedMemorySize, F_SMEM);

  prep_tabs<<<64, 128>>>(cheb1, cheb2, coefs);
  fused_all<<<dim3(LL, BB), 320, F_SMEM>>>(x, out);
}

// round 8
// speedup vs baseline: 5.7211x; 1.2294x over previous
#include <cuda_runtime.h>
#include <cuda_bf16.h>
#include <cstdint>

#define BB 32
#define CC 16
#define UU 16
#define LL 128
#define PW (LL*LL)
#define KP 5
#define MKC 80
#define MLU 80

// ------------------------------- scratch ------------------------------------
__device__ float         g_band1[LL*25];        // packed band of cheb1 [p][25]
__device__ float         g_band2T[25*LL];       // packed band of cheb2, transposed [j][q]
__device__ __nv_bfloat16 g_Chi[MLU*88];         // coef matrix split [m][kk pad 88]
__device__ __nv_bfloat16 g_Clo[MLU*88];

// --------------------------- helpers ------------------------------
__device__ __forceinline__ void cp16(uint32_t dst, const void* src){
  asm volatile("cp.async.cg.shared.global [%0], [%1], 16;" :: "r"(dst), "l"(src));
}
__device__ __forceinline__ void cp_commit(){ asm volatile("cp.async.commit_group;"); }
template<int N> __device__ __forceinline__ void cp_wait(){
  asm volatile("cp.async.wait_group %0;" :: "n"(N));
}
__device__ __forceinline__ uint32_t smem_u32(const void* p){
  return (uint32_t)__cvta_generic_to_shared(p);
}
__device__ __forceinline__ void bsplit(float v, __nv_bfloat16& h, __nv_bfloat16& l){
  h = __float2bfloat16(v);
  l = __float2bfloat16(v - __bfloat162float(h));
}
__device__ __forceinline__ void mma16816(float* d, const uint32_t* a, const uint32_t* b){
  asm volatile("mma.sync.aligned.m16n8k16.row.col.f32.bf16.bf16.f32 "
    "{%0,%1,%2,%3}, {%4,%5,%6,%7}, {%8,%9}, {%0,%1,%2,%3};"
    : "+f"(d[0]),"+f"(d[1]),"+f"(d[2]),"+f"(d[3])
    : "r"(a[0]),"r"(a[1]),"r"(a[2]),"r"(a[3]), "r"(b[0]),"r"(b[1]));
}
__device__ __forceinline__ void ldsm4(uint32_t* r, uint32_t addr){
  asm volatile("ldmatrix.sync.aligned.m8n8.x4.shared.b16 {%0,%1,%2,%3}, [%4];"
    : "=r"(r[0]),"=r"(r[1]),"=r"(r[2]),"=r"(r[3]) : "r"(addr));
}
__device__ __forceinline__ void ldsm4t(uint32_t* r, uint32_t addr){
  asm volatile("ldmatrix.sync.aligned.m8n8.x4.trans.shared.b16 {%0,%1,%2,%3}, [%4];"
    : "=r"(r[0]),"=r"(r[1]),"=r"(r[2]),"=r"(r[3]) : "r"(addr));
}

// ============================================================================
// Prep (parallel): band tables (T_k has bandwidth k — exact structural zeros)
// band1[p][k*k+k+d] = c1[k][p+d][p];  band2T[(k*k+k+d)][q] = c2[k][q+d][q]
// plus split coef matrix C[m=(l,u)][kk=(k1,c)] -> bf16 hi/lo, kk padded to 88.
// ============================================================================
__global__ void prep_tabs(const float* __restrict__ c1, const float* __restrict__ c2,
                          const float* __restrict__ coefs){
  int gt = blockIdx.x*128 + threadIdx.x;   // 64 x 128 = 8192
  if (gt < LL){
    int t = gt;
#pragma unroll
    for (int k = 0; k < KP; k++)
      for (int d = -k; d <= k; d++){
        int h = t + d;
        bool ok = (h >= 0 && h < LL);
        float v1 = ok ? c1[(k*LL + h)*LL + t] : 0.f;
        float v2 = ok ? c2[(k*LL + h)*LL + t] : 0.f;
        g_band1[t*25 + k*k + k + d] = v1;
        g_band2T[(k*k + k + d)*LL + t] = v2;
      }
  }
  for (int i = gt; i < MLU*88; i += 8192){
    int m = i / 88, kk = i % 88;
    float v = 0.f;
    if (kk < MKC){
      int l = m >> 4, u = m & 15, k1 = kk >> 4, c = kk & 15;
      v = coefs[((k1*KP + l)*CC + c)*UU + u];
    }
    __nv_bfloat16 h, l2;
    bsplit(v, h, l2);
    g_Chi[i] = h;
    g_Clo[i] = l2;
  }
}

// ============================================================================
// Fully fused kernel, one block per (b, p):
//   phase A (fp32 stencil): t1[kk][w] -> split bf16 hi/lo ldsm tiles in smem
//   phase B (HMMA 3-product): s[m=(l,u)][w] = sum_kk C[m][kk]*t1[kk][w]
//   phase C (vectorized stencil): out[b,u,p,q] = sum_{l,d} band2T*s
// SMEM: t1hi [80][136]bf16 | t1lo | Chi [80][88] | Clo | pad16 | s[80][132]f32 | pad16
// band2T (12.8KB) overlaid into dead t1hi region after MMA. 113984 B, occ 2.
// ============================================================================
#define F_T1H 0
#define F_T1L 21760
#define F_CH  43520
#define F_CL  57600
#define F_S   71680            // 16B front pad, then 80*132 f32, 16B back pad
#define F_SD  (F_S + 16)
#define F_SMEM 113984          // bytes

__global__ __launch_bounds__(320,2) void fused_all(const float* __restrict__ x,
                                                   float* __restrict__ out){
  extern __shared__ char smem[];
  uint32_t sb = smem_u32(smem);
  int tid = threadIdx.x, wid = tid >> 5, lane = tid & 31;
  int p = blockIdx.x, b = blockIdx.y;

  // ---- async C-tile loads (overlap with stencil below) ----
  for (int i = tid; i < 1760; i += 320){
    int var = (i >= 880);
    int j = i - var*880;
    int r = j / 11, ch = j % 11;
    const __nv_bfloat16* src = (var ? g_Clo : g_Chi) + r*88 + ch*8;
    cp16(sb + (var ? F_CL : F_CH) + r*176 + ch*16, src);
  }
  cp_commit();

  // ---- band1[p] broadcast into registers ----
  float bnd[25];
#pragma unroll
  for (int j = 0; j < 25; j++) bnd[j] = g_band1[p*25 + j];

  // ---- phase A: stage-1 stencil, registers -> split bf16 smem tiles ----
  for (int i = tid; i < 512; i += 320){
    int c  = i >> 5;
    int w4 = (i & 31) << 2;
    const float* xs = x + (size_t)(b*CC + c)*PW + w4;
    float4 win[9];
#pragma unroll
    for (int r = 0; r < 9; r++){
      int h = p - 4 + r;
      h = h < 0 ? 0 : (h > 127 ? 127 : h);
      win[r] = *(const float4*)(xs + h*LL);
    }
#pragma unroll
    for (int k = 0; k < KP; k++){
      float4 o = make_float4(0.f, 0.f, 0.f, 0.f);
#pragma unroll
      for (int d = -k; d <= k; d++){
        float cf = bnd[k*k + k + d];
        float4 v = win[4 + d];
        o.x = fmaf(cf, v.x, o.x);
        o.y = fmaf(cf, v.y, o.y);
        o.z = fmaf(cf, v.z, o.z);
        o.w = fmaf(cf, v.w, o.w);
      }
      __nv_bfloat16 h0,l0,h1,l1,h2,l2,h3,l3;
      bsplit(o.x,h0,l0); bsplit(o.y,h1,l1); bsplit(o.z,h2,l2); bsplit(o.w,h3,l3);
      uint2 hv = make_uint2((uint32_t)__bfloat16_as_ushort(h0) | ((uint32_t)__bfloat16_as_ushort(h1)<<16),
                            (uint32_t)__bfloat16_as_ushort(h2) | ((uint32_t)__bfloat16_as_ushort(h3)<<16));
      uint2 lv = make_uint2((uint32_t)__bfloat16_as_ushort(l0) | ((uint32_t)__bfloat16_as_ushort(l1)<<16),
                            (uint32_t)__bfloat16_as_ushort(l2) | ((uint32_t)__bfloat16_as_ushort(l3)<<16));
      uint32_t off = (uint32_t)((k*CC + c)*272 + w4*2);
      *(uint2*)(smem + F_T1H + off) = hv;
      *(uint2*)(smem + F_T1L + off) = lv;
    }
  }

  cp_wait<0>();
  __syncthreads();

  // ---- phase B: HMMA, 10 warps = 5 m-tiles x 2 n-halves, warp tile 16m x 64w
  int mi = wid >> 1, ni = wid & 1;
  float acc[8][4];
#pragma unroll
  for (int nt = 0; nt < 8; nt++)
#pragma unroll
    for (int j = 0; j < 4; j++) acc[nt][j] = 0.f;

  uint32_t arow = (uint32_t)(mi*16 + (lane & 15));
  uint32_t alh  = (uint32_t)((lane >> 4) * 16);
  uint32_t brow16 = (uint32_t)(lane & 15);
  uint32_t blh  = (uint32_t)((lane >> 4) * 16);

#pragma unroll
  for (int kt = 0; kt < 5; kt++){
    uint32_t a_h[4], a_l[4];
    uint32_t aaddr = arow*176 + (uint32_t)kt*32 + alh;
    ldsm4(a_h, sb + F_CH + aaddr);
    ldsm4(a_l, sb + F_CL + aaddr);
#pragma unroll
    for (int g = 0; g < 4; g++){
      uint32_t b_h[4], b_l[4];
      uint32_t baddr = ((uint32_t)kt*16 + brow16)*272 + (uint32_t)(ni*128 + g*32) + blh;
      ldsm4t(b_h, sb + F_T1H + baddr);
      ldsm4t(b_l, sb + F_T1L + baddr);
#pragma unroll
      for (int sub = 0; sub < 2; sub++){
        mma16816(acc[g*2+sub], a_h, b_h + sub*2);
        mma16816(acc[g*2+sub], a_h, b_l + sub*2);
        mma16816(acc[g*2+sub], a_l, b_h + sub*2);
      }
    }
  }

  __syncthreads();   // all warps done reading t1 tiles before band2T overlay

  // band2T table into dead t1hi region (async, overlapped with s-tile writes)
  for (int i = tid; i < 800; i += 320)
    cp16(sb + F_T1H + i*16, g_band2T + i*4);
  cp_commit();

  // accumulators -> s tile [80][132] f32 (+16B pads front/back, finite garbage OK)
  {
    float* sT = (float*)(smem + F_SD);
    int gid = lane >> 2, qc = (lane & 3)*2;
    int row = mi*16 + gid;
#pragma unroll
    for (int nt = 0; nt < 8; nt++){
      int col = ni*64 + nt*8 + qc;
      sT[row*132 + col]       = acc[nt][0];
      sT[row*132 + col + 1]   = acc[nt][1];
      sT[(row+8)*132 + col]   = acc[nt][2];
      sT[(row+8)*132 + col+1] = acc[nt][3];
    }
  }
  // zero the 4-float pads at region front and back
  if (tid < 4) ((float*)(smem + F_S))[tid] = 0.f;
  else if (tid < 8) ((float*)(smem + F_SD))[80*132 + tid - 4] = 0.f;

  cp_wait<0>();
  __syncthreads();

  // ---- phase C: vectorized stage-3 stencil ----
  // warp covers all 128 q (lane*4 each); loops its u values (u = wid, wid+10).
  // coef rows loaded once per l (shared across u); s windows as 3x LDS.128.
  {
    const float* bT = (const float*)(smem + F_T1H);   // [25][128]
    const float* sT = (const float*)(smem + F_SD);    // [80][132]
    int q4 = lane*4;
    float o[2][4];
#pragma unroll
    for (int s2 = 0; s2 < 2; s2++)
#pragma unroll
      for (int j = 0; j < 4; j++) o[s2][j] = 0.f;

#pragma unroll
    for (int l = 0; l < KP; l++){
      const int nd = 2*l + 1;
      float4 cj[9];
#pragma unroll
      for (int dd = 0; dd < nd; dd++)
        cj[dd] = *(const float4*)(bT + (l*l + dd)*LL + q4);
#pragma unroll
      for (int s2 = 0; s2 < 2; s2++){
        int u = wid + s2*10;
        if (u < UU){
          const float* srow = sT + (l*UU + u)*132;
          float4 w0 = *(const float4*)(srow + q4 - 4);
          float4 w1 = *(const float4*)(srow + q4);
          float4 w2 = *(const float4*)(srow + q4 + 4);
          float w[12] = {w0.x,w0.y,w0.z,w0.w, w1.x,w1.y,w1.z,w1.w, w2.x,w2.y,w2.z,w2.w};
#pragma unroll
          for (int j = 0; j < 4; j++)
#pragma unroll
            for (int dd = 0; dd < nd; dd++)
              o[s2][j] = fmaf(((const float*)&cj[dd])[j], w[4 + j + dd - l], o[s2][j]);
        }
      }
    }
#pragma unroll
    for (int s2 = 0; s2 < 2; s2++){
      int u = wid + s2*10;
      if (u < UU)
        *(float4*)(out + ((size_t)(b*UU + u)*LL + p)*LL + q4) =
            make_float4(o[s2][0], o[s2][1], o[s2][2], o[s2][3]);
    }
  }
}

// ============================================================================
extern "C" void kernel_launch(void* const* d_in, const int* in_sizes, int n_in,
                              void* d_out, int out_size)
{
  const float* x = nullptr;
  const float* coefs = nullptr;
  const float* cheb1 = nullptr;
  const float* cheb2 = nullptr;
  for (int i = 0; i < n_in; i++){
    int sz = in_sizes[i];
    const float* p = (const float*)d_in[i];
    if (sz == BB*CC*PW)            x = p;
    else if (sz == KP*KP*CC*UU)    coefs = p;
    else if (sz == KP*PW){ if (!cheb1) cheb1 = p; else cheb2 = p; }
  }
  if (!cheb2) cheb2 = cheb1;
  float* out = (float*)d_out;

  cudaFuncSetAttribute(fused_all, cudaFuncAttributeMaxDynamicSharedMemorySize, F_SMEM);

  prep_tabs<<<64, 128>>>(cheb1, cheb2, coefs);
  fused_all<<<dim3(LL, BB), 320, F_SMEM>>>(x, out);
}

// round 9
// speedup vs baseline: 5.9509x; 1.0402x over previous
#include <cuda_runtime.h>
#include <cuda_bf16.h>
#include <cstdint>

#define BB 32
#define CC 16
#define UU 16
#define LL 128
#define PW (LL*LL)
#define KP 5
#define MKC 80
#define MLU 80

// ------------------------------- scratch ------------------------------------
__device__ float         g_band1[LL*25];        // packed band of cheb1 [p][25]
__device__ float         g_band2T[25*LL];       // packed band of cheb2, transposed [j][q]
__device__ __nv_bfloat16 g_Chi[MLU*88];         // coef matrix split [m][kk pad 88]
__device__ __nv_bfloat16 g_Clo[MLU*88];

// --------------------------- helpers ------------------------------
__device__ __forceinline__ void cp16(uint32_t dst, const void* src){
  asm volatile("cp.async.cg.shared.global [%0], [%1], 16;" :: "r"(dst), "l"(src));
}
__device__ __forceinline__ void cp_commit(){ asm volatile("cp.async.commit_group;"); }
template<int N> __device__ __forceinline__ void cp_wait(){
  asm volatile("cp.async.wait_group %0;" :: "n"(N));
}
__device__ __forceinline__ uint32_t smem_u32(const void* p){
  return (uint32_t)__cvta_generic_to_shared(p);
}
__device__ __forceinline__ void bsplit(float v, __nv_bfloat16& h, __nv_bfloat16& l){
  h = __float2bfloat16(v);
  l = __float2bfloat16(v - __bfloat162float(h));
}
__device__ __forceinline__ void mma16816(float* d, const uint32_t* a, const uint32_t* b){
  asm volatile("mma.sync.aligned.m16n8k16.row.col.f32.bf16.bf16.f32 "
    "{%0,%1,%2,%3}, {%4,%5,%6,%7}, {%8,%9}, {%0,%1,%2,%3};"
    : "+f"(d[0]),"+f"(d[1]),"+f"(d[2]),"+f"(d[3])
    : "r"(a[0]),"r"(a[1]),"r"(a[2]),"r"(a[3]), "r"(b[0]),"r"(b[1]));
}
__device__ __forceinline__ void ldsm4(uint32_t* r, uint32_t addr){
  asm volatile("ldmatrix.sync.aligned.m8n8.x4.shared.b16 {%0,%1,%2,%3}, [%4];"
    : "=r"(r[0]),"=r"(r[1]),"=r"(r[2]),"=r"(r[3]) : "r"(addr));
}
__device__ __forceinline__ void ldsm4t(uint32_t* r, uint32_t addr){
  asm volatile("ldmatrix.sync.aligned.m8n8.x4.trans.shared.b16 {%0,%1,%2,%3}, [%4];"
    : "=r"(r[0]),"=r"(r[1]),"=r"(r[2]),"=r"(r[3]) : "r"(addr));
}

// ============================================================================
// Prep (parallel): band tables (T_k has bandwidth k — exact structural zeros)
// band1[p][k*k+k+d] = c1[k][p+d][p];  band2T[(k*k+k+d)][q] = c2[k][q+d][q]
// plus split coef matrix C[m=(l,u)][kk=(k1,c)] -> bf16 hi/lo, kk padded to 88.
// ============================================================================
__global__ void prep_tabs(const float* __restrict__ c1, const float* __restrict__ c2,
                          const float* __restrict__ coefs){
  int gt = blockIdx.x*128 + threadIdx.x;   // 64 x 128 = 8192
  if (gt < LL){
    int t = gt;
#pragma unroll
    for (int k = 0; k < KP; k++)
      for (int d = -k; d <= k; d++){
        int h = t + d;
        bool ok = (h >= 0 && h < LL);
        g_band1[t*25 + k*k + k + d] = ok ? c1[(k*LL + h)*LL + t] : 0.f;
        g_band2T[(k*k + k + d)*LL + t] = ok ? c2[(k*LL + h)*LL + t] : 0.f;
      }
  }
  for (int i = gt; i < MLU*88; i += 8192){
    int m = i / 88, kk = i % 88;
    float v = 0.f;
    if (kk < MKC){
      int l = m >> 4, u = m & 15, k1 = kk >> 4, c = kk & 15;
      v = coefs[((k1*KP + l)*CC + c)*UU + u];
    }
    __nv_bfloat16 h, l2;
    bsplit(v, h, l2);
    g_Chi[i] = h;
    g_Clo[i] = l2;
  }
}

// ============================================================================
// Fully fused kernel, one block per (b, p):
//   phase A (fp32 stencil, d-major): t1[kk][w] -> split bf16 hi/lo ldsm tiles
//   phase B (HMMA 3-product): s[m=(l,u)][w] = sum_kk C[m][kk]*t1[kk][w]
//   phase C (vectorized stencil): out[b,u,p,q] = sum_{l,d} band2T*s
// SMEM (71808 B, occ 3):
//   phase A/B: t1hi[80][136]bf16 | t1lo | Chi[80][88] | Clo | band1[32]
//   phase C (overlay after MMA): s[80][132]f32 (+pads) over t1 region,
//                                band2T[25][128] over C region.
// ============================================================================
#define F_T1H 0
#define F_T1L 21760
#define F_CH  43520
#define F_CL  57600
#define F_BND1 71680
#define F_SMEM 71808           // bytes
// phase-C overlays
#define F_S   0                // 16B front pad, then 80*132 f32, 16B back pad
#define F_SD  (F_S + 16)
#define F_B2  43520            // band2T [25][128] f32

__global__ __launch_bounds__(320,3) void fused_all(const float* __restrict__ x,
                                                   float* __restrict__ out){
  extern __shared__ char smem[];
  uint32_t sb = smem_u32(smem);
  int tid = threadIdx.x, wid = tid >> 5, lane = tid & 31;
  int p = blockIdx.x, b = blockIdx.y;

  // ---- async C-tile loads (overlap with stencil below) ----
  for (int i = tid; i < 1760; i += 320){
    int var = (i >= 880);
    int j = i - var*880;
    int r = j / 11, ch = j % 11;
    const __nv_bfloat16* src = (var ? g_Clo : g_Chi) + r*88 + ch*8;
    cp16(sb + (var ? F_CL : F_CH) + r*176 + ch*16, src);
  }
  cp_commit();

  // ---- band1[p] into smem (broadcast table for phase A) ----
  float* bnd_s = (float*)(smem + F_BND1);
  if (tid < 25) bnd_s[tid] = g_band1[p*25 + tid];
  __syncthreads();

  // ---- phase A: stage-1 stencil, d-major (low register pressure) ----
  // 512 tasks = 16 c x 32 w-quads; 5 k-accumulators, one x row in flight.
  for (int i = tid; i < 512; i += 320){
    int c  = i >> 5;
    int w4 = (i & 31) << 2;
    const float* xs = x + (size_t)(b*CC + c)*PW + w4;
    float4 acck[5];
#pragma unroll
    for (int k = 0; k < KP; k++) acck[k] = make_float4(0.f,0.f,0.f,0.f);
#pragma unroll
    for (int d = -4; d <= 4; d++){
      int h = p + d;
      h = h < 0 ? 0 : (h > 127 ? 127 : h);
      float4 v = *(const float4*)(xs + h*LL);
      int ad = d < 0 ? -d : d;
#pragma unroll
      for (int k = 0; k < KP; k++){
        if (k >= ad){
          float cf = bnd_s[k*k + k + d];
          acck[k].x = fmaf(cf, v.x, acck[k].x);
          acck[k].y = fmaf(cf, v.y, acck[k].y);
          acck[k].z = fmaf(cf, v.z, acck[k].z);
          acck[k].w = fmaf(cf, v.w, acck[k].w);
        }
      }
    }
#pragma unroll
    for (int k = 0; k < KP; k++){
      float4 o = acck[k];
      __nv_bfloat16 h0,l0,h1,l1,h2,l2,h3,l3;
      bsplit(o.x,h0,l0); bsplit(o.y,h1,l1); bsplit(o.z,h2,l2); bsplit(o.w,h3,l3);
      uint2 hv = make_uint2((uint32_t)__bfloat16_as_ushort(h0) | ((uint32_t)__bfloat16_as_ushort(h1)<<16),
                            (uint32_t)__bfloat16_as_ushort(h2) | ((uint32_t)__bfloat16_as_ushort(h3)<<16));
      uint2 lv = make_uint2((uint32_t)__bfloat16_as_ushort(l0) | ((uint32_t)__bfloat16_as_ushort(l1)<<16),
                            (uint32_t)__bfloat16_as_ushort(l2) | ((uint32_t)__bfloat16_as_ushort(l3)<<16));
      uint32_t off = (uint32_t)((k*CC + c)*272 + w4*2);
      *(uint2*)(smem + F_T1H + off) = hv;
      *(uint2*)(smem + F_T1L + off) = lv;
    }
  }

  cp_wait<0>();
  __syncthreads();

  // ---- phase B: HMMA, 10 warps = 5 m-tiles x 2 n-halves, warp tile 16m x 64w
  int mi = wid >> 1, ni = wid & 1;
  float acc[8][4];
#pragma unroll
  for (int nt = 0; nt < 8; nt++)
#pragma unroll
    for (int j = 0; j < 4; j++) acc[nt][j] = 0.f;

  uint32_t arow = (uint32_t)(mi*16 + (lane & 15));
  uint32_t alh  = (uint32_t)((lane >> 4) * 16);
  uint32_t brow16 = (uint32_t)(lane & 15);
  uint32_t blh  = (uint32_t)((lane >> 4) * 16);

#pragma unroll
  for (int kt = 0; kt < 5; kt++){
    uint32_t a_h[4], a_l[4];
    uint32_t aaddr = arow*176 + (uint32_t)kt*32 + alh;
    ldsm4(a_h, sb + F_CH + aaddr);
    ldsm4(a_l, sb + F_CL + aaddr);
#pragma unroll
    for (int g = 0; g < 4; g++){
      uint32_t b_h[4], b_l[4];
      uint32_t baddr = ((uint32_t)kt*16 + brow16)*272 + (uint32_t)(ni*128 + g*32) + blh;
      ldsm4t(b_h, sb + F_T1H + baddr);
      ldsm4t(b_l, sb + F_T1L + baddr);
#pragma unroll
      for (int sub = 0; sub < 2; sub++){
        mma16816(acc[g*2+sub], a_h, b_h + sub*2);
        mma16816(acc[g*2+sub], a_h, b_l + sub*2);
        mma16816(acc[g*2+sub], a_l, b_h + sub*2);
      }
    }
  }

  __syncthreads();   // t1 + C tiles fully consumed; overlays become legal

  // band2T into dead C region (async, overlapped with s-tile writes)
  for (int i = tid; i < 800; i += 320)
    cp16(sb + F_B2 + i*16, g_band2T + i*4);
  cp_commit();

  // accumulators -> s tile [80][132] f32 overlaid on t1 region
  {
    float* sT = (float*)(smem + F_SD);
    int gid = lane >> 2, qc = (lane & 3)*2;
    int row = mi*16 + gid;
#pragma unroll
    for (int nt = 0; nt < 8; nt++){
      int col = ni*64 + nt*8 + qc;
      sT[row*132 + col]       = acc[nt][0];
      sT[row*132 + col + 1]   = acc[nt][1];
      sT[(row+8)*132 + col]   = acc[nt][2];
      sT[(row+8)*132 + col+1] = acc[nt][3];
    }
  }
  // zero the 4-float pads at region front and back
  if (tid < 4) ((float*)(smem + F_S))[tid] = 0.f;
  else if (tid < 8) ((float*)(smem + F_SD))[80*132 + tid - 4] = 0.f;

  cp_wait<0>();
  __syncthreads();

  // ---- phase C: vectorized stage-3 stencil ----
  // warp covers all 128 q (lane*4 each); loops its u values (u = wid, wid+10).
  {
    const float* bT = (const float*)(smem + F_B2);    // [25][128]
    const float* sT = (const float*)(smem + F_SD);    // [80][132]
    int q4 = lane*4;
    float o[2][4];
#pragma unroll
    for (int s2 = 0; s2 < 2; s2++)
#pragma unroll
      for (int j = 0; j < 4; j++) o[s2][j] = 0.f;

#pragma unroll
    for (int l = 0; l < KP; l++){
      const int nd = 2*l + 1;
      float4 cj[9];
#pragma unroll
      for (int dd = 0; dd < nd; dd++)
        cj[dd] = *(const float4*)(bT + (l*l + dd)*LL + q4);
#pragma unroll
      for (int s2 = 0; s2 < 2; s2++){
        int u = wid + s2*10;
        if (u < UU){
          const float* srow = sT + (l*UU + u)*132;
          float4 w0 = *(const float4*)(srow + q4 - 4);
          float4 w1 = *(const float4*)(srow + q4);
          float4 w2 = *(const float4*)(srow + q4 + 4);
          float w[12] = {w0.x,w0.y,w0.z,w0.w, w1.x,w1.y,w1.z,w1.w, w2.x,w2.y,w2.z,w2.w};
#pragma unroll
          for (int j = 0; j < 4; j++)
#pragma unroll
            for (int dd = 0; dd < nd; dd++)
              o[s2][j] = fmaf(((const float*)&cj[dd])[j], w[4 + j + dd - l], o[s2][j]);
        }
      }
    }
#pragma unroll
    for (int s2 = 0; s2 < 2; s2++){
      int u = wid + s2*10;
      if (u < UU)
        *(float4*)(out + ((size_t)(b*UU + u)*LL + p)*LL + q4) =
            make_float4(o[s2][0], o[s2][1], o[s2][2], o[s2][3]);
    }
  }
}

// ============================================================================
extern "C" void kernel_launch(void* const* d_in, const int* in_sizes, int n_in,
                              void* d_out, int out_size)
{
  const float* x = nullptr;
  const float* coefs = nullptr;
  const float* cheb1 = nullptr;
  const float* cheb2 = nullptr;
  for (int i = 0; i < n_in; i++){
    int sz = in_sizes[i];
    const float* p = (const float*)d_in[i];
    if (sz == BB*CC*PW)            x = p;
    else if (sz == KP*KP*CC*UU)    coefs = p;
    else if (sz == KP*PW){ if (!cheb1) cheb1 = p; else cheb2 = p; }
  }
  if (!cheb2) cheb2 = cheb1;
  float* out = (float*)d_out;

  cudaFuncSetAttribute(fused_all, cudaFuncAttributeMaxDynamicSharedMemorySize, F_SMEM);

  prep_tabs<<<64, 128>>>(cheb1, cheb2, coefs);
  fused_all<<<dim3(LL, BB), 320, F_SMEM>>>(x, out);
}

// round 10
// speedup vs baseline: 6.2697x; 1.0536x over previous
#include <cuda_runtime.h>
#include <cuda_bf16.h>
#include <cstdint>

#define BB 32
#define CC 16
#define UU 16
#define LL 128
#define PW (LL*LL)
#define KP 5
#define MKC 80
#define MLU 80

// ------------------------------- scratch ------------------------------------
__device__ float         g_band1[LL*25];        // packed band of cheb1 [p][25]
__device__ float         g_band2T[25*LL];       // packed band of cheb2, transposed [j][q]
__device__ __nv_bfloat16 g_Chi[MLU*88];         // coef matrix split [m][kk pad 88]
__device__ __nv_bfloat16 g_Clo[MLU*88];

// --------------------------- helpers ------------------------------
__device__ __forceinline__ void cp16(uint32_t dst, const void* src){
  asm volatile("cp.async.cg.shared.global [%0], [%1], 16;" :: "r"(dst), "l"(src));
}
__device__ __forceinline__ void cp_commit(){ asm volatile("cp.async.commit_group;"); }
template<int N> __device__ __forceinline__ void cp_wait(){
  asm volatile("cp.async.wait_group %0;" :: "n"(N));
}
__device__ __forceinline__ uint32_t smem_u32(const void* p){
  return (uint32_t)__cvta_generic_to_shared(p);
}
__device__ __forceinline__ void bsplit(float v, __nv_bfloat16& h, __nv_bfloat16& l){
  h = __float2bfloat16(v);
  l = __float2bfloat16(v - __bfloat162float(h));
}
__device__ __forceinline__ void mma16816(float* d, const uint32_t* a, const uint32_t* b){
  asm volatile("mma.sync.aligned.m16n8k16.row.col.f32.bf16.bf16.f32 "
    "{%0,%1,%2,%3}, {%4,%5,%6,%7}, {%8,%9}, {%0,%1,%2,%3};"
    : "+f"(d[0]),"+f"(d[1]),"+f"(d[2]),"+f"(d[3])
    : "r"(a[0]),"r"(a[1]),"r"(a[2]),"r"(a[3]), "r"(b[0]),"r"(b[1]));
}
__device__ __forceinline__ void ldsm4(uint32_t* r, uint32_t addr){
  asm volatile("ldmatrix.sync.aligned.m8n8.x4.shared.b16 {%0,%1,%2,%3}, [%4];"
    : "=r"(r[0]),"=r"(r[1]),"=r"(r[2]),"=r"(r[3]) : "r"(addr));
}
__device__ __forceinline__ void ldsm4t(uint32_t* r, uint32_t addr){
  asm volatile("ldmatrix.sync.aligned.m8n8.x4.trans.shared.b16 {%0,%1,%2,%3}, [%4];"
    : "=r"(r[0]),"=r"(r[1]),"=r"(r[2]),"=r"(r[3]) : "r"(addr));
}

// ============================================================================
// Prep (parallel): band tables (T_k has bandwidth k — exact structural zeros)
// band1[p][k*k+k+d] = c1[k][p+d][p];  band2T[(k*k+k+d)][q] = c2[k][q+d][q]
// plus split coef matrix C[m=(l,u)][kk=(k1,c)] -> bf16 hi/lo, kk padded to 88.
// ============================================================================
__global__ void prep_tabs(const float* __restrict__ c1, const float* __restrict__ c2,
                          const float* __restrict__ coefs){
  int gt = blockIdx.x*128 + threadIdx.x;   // 64 x 128 = 8192
  if (gt < LL){
    int t = gt;
#pragma unroll
    for (int k = 0; k < KP; k++)
      for (int d = -k; d <= k; d++){
        int h = t + d;
        bool ok = (h >= 0 && h < LL);
        g_band1[t*25 + k*k + k + d] = ok ? c1[(k*LL + h)*LL + t] : 0.f;
        g_band2T[(k*k + k + d)*LL + t] = ok ? c2[(k*LL + h)*LL + t] : 0.f;
      }
  }
  for (int i = gt; i < MLU*88; i += 8192){
    int m = i / 88, kk = i % 88;
    float v = 0.f;
    if (kk < MKC){
      int l = m >> 4, u = m & 15, k1 = kk >> 4, c = kk & 15;
      v = coefs[((k1*KP + l)*CC + c)*UU + u];
    }
    __nv_bfloat16 h, l2;
    bsplit(v, h, l2);
    g_Chi[i] = h;
    g_Clo[i] = l2;
  }
}

// ============================================================================
// Fully fused kernel, one block per (b, p):
//   phase A (fp32 stencil, d-major): t1[kk][w] -> split bf16 hi/lo ldsm tiles
//   phase B (HMMA 3-product): s[m=(l,u)][w] = sum_kk C[m][kk]*t1[kk][w]
//   phase C (shfl-windowed stencil): out[b,u,p,q] = sum_{l,d} band2T*s
// SMEM (71808 B, occ 3):
//   phase A/B: t1hi[80][136]bf16 | t1lo | Chi[80][88] | Clo | band1[32]
//   phase C (overlay after MMA): s[80][132]f32 over t1 region,
//                                band2T[25][128] over C region.
// ============================================================================
#define F_T1H 0
#define F_T1L 21760
#define F_CH  43520
#define F_CL  57600
#define F_BND1 71680
#define F_SMEM 71808           // bytes
// phase-C overlays
#define F_SD  16               // s tile [80][132] f32 (16B offset kept for alignment)
#define F_B2  43520            // band2T [25][128] f32

__global__ __launch_bounds__(320,3) void fused_all(const float* __restrict__ x,
                                                   float* __restrict__ out){
  extern __shared__ char smem[];
  uint32_t sb = smem_u32(smem);
  int tid = threadIdx.x, wid = tid >> 5, lane = tid & 31;
  int p = blockIdx.x, b = blockIdx.y;

  // ---- async C-tile loads (overlap with stencil below) ----
  for (int i = tid; i < 1760; i += 320){
    int var = (i >= 880);
    int j = i - var*880;
    int r = j / 11, ch = j % 11;
    const __nv_bfloat16* src = (var ? g_Clo : g_Chi) + r*88 + ch*8;
    cp16(sb + (var ? F_CL : F_CH) + r*176 + ch*16, src);
  }
  cp_commit();

  // ---- band1[p] into smem (broadcast table for phase A) ----
  float* bnd_s = (float*)(smem + F_BND1);
  if (tid < 25) bnd_s[tid] = g_band1[p*25 + tid];
  __syncthreads();

  // ---- phase A: stage-1 stencil, d-major (low register pressure) ----
  for (int i = tid; i < 512; i += 320){
    int c  = i >> 5;
    int w4 = (i & 31) << 2;
    const float* xs = x + (size_t)(b*CC + c)*PW + w4;
    float4 acck[5];
#pragma unroll
    for (int k = 0; k < KP; k++) acck[k] = make_float4(0.f,0.f,0.f,0.f);
#pragma unroll
    for (int d = -4; d <= 4; d++){
      int h = p + d;
      h = h < 0 ? 0 : (h > 127 ? 127 : h);
      float4 v = *(const float4*)(xs + h*LL);
      int ad = d < 0 ? -d : d;
#pragma unroll
      for (int k = 0; k < KP; k++){
        if (k >= ad){
          float cf = bnd_s[k*k + k + d];
          acck[k].x = fmaf(cf, v.x, acck[k].x);
          acck[k].y = fmaf(cf, v.y, acck[k].y);
          acck[k].z = fmaf(cf, v.z, acck[k].z);
          acck[k].w = fmaf(cf, v.w, acck[k].w);
        }
      }
    }
#pragma unroll
    for (int k = 0; k < KP; k++){
      float4 o = acck[k];
      __nv_bfloat16 h0,l0,h1,l1,h2,l2,h3,l3;
      bsplit(o.x,h0,l0); bsplit(o.y,h1,l1); bsplit(o.z,h2,l2); bsplit(o.w,h3,l3);
      uint2 hv = make_uint2((uint32_t)__bfloat16_as_ushort(h0) | ((uint32_t)__bfloat16_as_ushort(h1)<<16),
                            (uint32_t)__bfloat16_as_ushort(h2) | ((uint32_t)__bfloat16_as_ushort(h3)<<16));
      uint2 lv = make_uint2((uint32_t)__bfloat16_as_ushort(l0) | ((uint32_t)__bfloat16_as_ushort(l1)<<16),
                            (uint32_t)__bfloat16_as_ushort(l2) | ((uint32_t)__bfloat16_as_ushort(l3)<<16));
      uint32_t off = (uint32_t)((k*CC + c)*272 + w4*2);
      *(uint2*)(smem + F_T1H + off) = hv;
      *(uint2*)(smem + F_T1L + off) = lv;
    }
  }

  cp_wait<0>();
  __syncthreads();

  // ---- phase B: HMMA, 10 warps = 5 m-tiles x 2 n-halves, warp tile 16m x 64w
  int mi = wid >> 1, ni = wid & 1;
  float acc[8][4];
#pragma unroll
  for (int nt = 0; nt < 8; nt++)
#pragma unroll
    for (int j = 0; j < 4; j++) acc[nt][j] = 0.f;

  uint32_t arow = (uint32_t)(mi*16 + (lane & 15));
  uint32_t alh  = (uint32_t)((lane >> 4) * 16);
  uint32_t brow16 = (uint32_t)(lane & 15);
  uint32_t blh  = (uint32_t)((lane >> 4) * 16);

#pragma unroll
  for (int kt = 0; kt < 5; kt++){
    uint32_t a_h[4], a_l[4];
    uint32_t aaddr = arow*176 + (uint32_t)kt*32 + alh;
    ldsm4(a_h, sb + F_CH + aaddr);
    ldsm4(a_l, sb + F_CL + aaddr);
#pragma unroll
    for (int g = 0; g < 4; g++){
      uint32_t b_h[4], b_l[4];
      uint32_t baddr = ((uint32_t)kt*16 + brow16)*272 + (uint32_t)(ni*128 + g*32) + blh;
      ldsm4t(b_h, sb + F_T1H + baddr);
      ldsm4t(b_l, sb + F_T1L + baddr);
#pragma unroll
      for (int sub = 0; sub < 2; sub++){
        mma16816(acc[g*2+sub], a_h, b_h + sub*2);
        mma16816(acc[g*2+sub], a_h, b_l + sub*2);
        mma16816(acc[g*2+sub], a_l, b_h + sub*2);
      }
    }
  }

  __syncthreads();   // t1 + C tiles fully consumed; overlays become legal

  // band2T into dead C region (async, overlapped with s-tile writes)
  for (int i = tid; i < 800; i += 320)
    cp16(sb + F_B2 + i*16, g_band2T + i*4);
  cp_commit();

  // accumulators -> s tile [80][132] f32 overlaid on t1 region
  {
    float* sT = (float*)(smem + F_SD);
    int gid = lane >> 2, qc = (lane & 3)*2;
    int row = mi*16 + gid;
#pragma unroll
    for (int nt = 0; nt < 8; nt++){
      int col = ni*64 + nt*8 + qc;
      sT[row*132 + col]       = acc[nt][0];
      sT[row*132 + col + 1]   = acc[nt][1];
      sT[(row+8)*132 + col]   = acc[nt][2];
      sT[(row+8)*132 + col+1] = acc[nt][3];
    }
  }
  cp_wait<0>();
  __syncthreads();

  // ---- phase C: stage-3 stencil, shfl-windowed; warps 0-7, u = wid, wid+8 ----
  // Each lane owns q = lane*4..lane*4+3; edge neighbors come from shfl (lanes
  // 0/31 receive garbage there, multiplied by exactly-zero band coefficients).
  if (wid < 8){
    const float* bT = (const float*)(smem + F_B2);    // [25][128]
    const float* sT = (const float*)(smem + F_SD);    // [80][132]
    int q4 = lane*4;
    float o[2][4];
#pragma unroll
    for (int s2 = 0; s2 < 2; s2++)
#pragma unroll
      for (int j = 0; j < 4; j++) o[s2][j] = 0.f;

#pragma unroll
    for (int l = 0; l < KP; l++){
      const int nd = 2*l + 1;
      float4 cj[9];
#pragma unroll
      for (int dd = 0; dd < nd; dd++)
        cj[dd] = *(const float4*)(bT + (l*l + dd)*LL + q4);
#pragma unroll
      for (int s2 = 0; s2 < 2; s2++){
        int u = wid + s2*8;
        const float* srow = sT + (l*UU + u)*132;
        float4 v = *(const float4*)(srow + q4);
        float4 wm, wp;
        wm.x = __shfl_up_sync(0xffffffffu, v.x, 1);
        wm.y = __shfl_up_sync(0xffffffffu, v.y, 1);
        wm.z = __shfl_up_sync(0xffffffffu, v.z, 1);
        wm.w = __shfl_up_sync(0xffffffffu, v.w, 1);
        wp.x = __shfl_down_sync(0xffffffffu, v.x, 1);
        wp.y = __shfl_down_sync(0xffffffffu, v.y, 1);
        wp.z = __shfl_down_sync(0xffffffffu, v.z, 1);
        wp.w = __shfl_down_sync(0xffffffffu, v.w, 1);
        float w[12] = {wm.x,wm.y,wm.z,wm.w, v.x,v.y,v.z,v.w, wp.x,wp.y,wp.z,wp.w};
#pragma unroll
        for (int j = 0; j < 4; j++)
#pragma unroll
          for (int dd = 0; dd < nd; dd++)
            o[s2][j] = fmaf(((const float*)&cj[dd])[j], w[4 + j + dd - l], o[s2][j]);
      }
    }
#pragma unroll
    for (int s2 = 0; s2 < 2; s2++){
      int u = wid + s2*8;
      *(float4*)(out + ((size_t)(b*UU + u)*LL + p)*LL + q4) =
          make_float4(o[s2][0], o[s2][1], o[s2][2], o[s2][3]);
    }
  }
}

// ============================================================================
extern "C" void kernel_launch(void* const* d_in, const int* in_sizes, int n_in,
                              void* d_out, int out_size)
{
  const float* x = nullptr;
  const float* coefs = nullptr;
  const float* cheb1 = nullptr;
  const float* cheb2 = nullptr;
  for (int i = 0; i < n_in; i++){
    int sz = in_sizes[i];
    const float* p = (const float*)d_in[i];
    if (sz == BB*CC*PW)            x = p;
    else if (sz == KP*KP*CC*UU)    coefs = p;
    else if (sz == KP*PW){ if (!cheb1) cheb1 = p; else cheb2 = p; }
  }
  if (!cheb2) cheb2 = cheb1;
  float* out = (float*)d_out;

  cudaFuncSetAttribute(fused_all, cudaFuncAttributeMaxDynamicSharedMemorySize, F_SMEM);

  prep_tabs<<<64, 128>>>(cheb1, cheb2, coefs);
  fused_all<<<dim3(LL, BB), 320, F_SMEM>>>(x, out);
}

// round 11
// speedup vs baseline: 6.5343x; 1.0422x over previous
#include <cuda_runtime.h>
#include <cuda_bf16.h>
#include <cstdint>

#define BB 32
#define CC 16
#define UU 16
#define LL 128
#define PW (LL*LL)
#define KP 5
#define MKC 80
#define MLU 80

// ------------------------------- scratch ------------------------------------
__device__ float         g_band1[LL*25];        // packed band of cheb1 [p][25]
__device__ float         g_band2T[25*LL];       // packed band of cheb2, transposed [j][q]
__device__ __nv_bfloat16 g_Chi[MLU*88];         // coef matrix split [m][kk pad 88]
__device__ __nv_bfloat16 g_Clo[MLU*88];

// --------------------------- helpers ------------------------------
__device__ __forceinline__ void cp16(uint32_t dst, const void* src){
  asm volatile("cp.async.cg.shared.global [%0], [%1], 16;" :: "r"(dst), "l"(src));
}
__device__ __forceinline__ void cp_commit(){ asm volatile("cp.async.commit_group;"); }
template<int N> __device__ __forceinline__ void cp_wait(){
  asm volatile("cp.async.wait_group %0;" :: "n"(N));
}
__device__ __forceinline__ uint32_t smem_u32(const void* p){
  return (uint32_t)__cvta_generic_to_shared(p);
}
__device__ __forceinline__ void bsplit(float v, __nv_bfloat16& h, __nv_bfloat16& l){
  h = __float2bfloat16(v);
  l = __float2bfloat16(v - __bfloat162float(h));
}
__device__ __forceinline__ void mma16816(float* d, const uint32_t* a, const uint32_t* b){
  asm volatile("mma.sync.aligned.m16n8k16.row.col.f32.bf16.bf16.f32 "
    "{%0,%1,%2,%3}, {%4,%5,%6,%7}, {%8,%9}, {%0,%1,%2,%3};"
    : "+f"(d[0]),"+f"(d[1]),"+f"(d[2]),"+f"(d[3])
    : "r"(a[0]),"r"(a[1]),"r"(a[2]),"r"(a[3]), "r"(b[0]),"r"(b[1]));
}
__device__ __forceinline__ void ldsm4(uint32_t* r, uint32_t addr){
  asm volatile("ldmatrix.sync.aligned.m8n8.x4.shared.b16 {%0,%1,%2,%3}, [%4];"
    : "=r"(r[0]),"=r"(r[1]),"=r"(r[2]),"=r"(r[3]) : "r"(addr));
}
__device__ __forceinline__ void ldsm4t(uint32_t* r, uint32_t addr){
  asm volatile("ldmatrix.sync.aligned.m8n8.x4.trans.shared.b16 {%0,%1,%2,%3}, [%4];"
    : "=r"(r[0]),"=r"(r[1]),"=r"(r[2]),"=r"(r[3]) : "r"(addr));
}

// ============================================================================
// Prep (parallel): band tables (T_k has bandwidth k — exact structural zeros)
// band1[p][k*k+k+d] = c1[k][p+d][p];  band2T[(k*k+k+d)][q] = c2[k][q+d][q]
// plus split coef matrix C[m=(l,u)][kk=(k1,c)] -> bf16 hi/lo, kk padded to 88.
// ============================================================================
__global__ void prep_tabs(const float* __restrict__ c1, const float* __restrict__ c2,
                          const float* __restrict__ coefs){
  int gt = blockIdx.x*128 + threadIdx.x;   // 64 x 128 = 8192
  if (gt < LL){
    int t = gt;
#pragma unroll
    for (int k = 0; k < KP; k++)
      for (int d = -k; d <= k; d++){
        int h = t + d;
        bool ok = (h >= 0 && h < LL);
        g_band1[t*25 + k*k + k + d] = ok ? c1[(k*LL + h)*LL + t] : 0.f;
        g_band2T[(k*k + k + d)*LL + t] = ok ? c2[(k*LL + h)*LL + t] : 0.f;
      }
  }
  for (int i = gt; i < MLU*88; i += 8192){
    int m = i / 88, kk = i % 88;
    float v = 0.f;
    if (kk < MKC){
      int l = m >> 4, u = m & 15, k1 = kk >> 4, c = kk & 15;
      v = coefs[((k1*KP + l)*CC + c)*UU + u];
    }
    __nv_bfloat16 h, l2;
    bsplit(v, h, l2);
    g_Chi[i] = h;
    g_Clo[i] = l2;
  }
}

// ============================================================================
// Fully fused kernel, one block per (b, p):
//   phase A (fp32 stencil, d-major): t1[kk][w] -> split bf16 hi/lo ldsm tiles
//   phase B (HMMA 3-product): s[m=(l,u)][w] = sum_kk C[m][kk]*t1[kk][w]
//   phase C (shfl-windowed stencil, 4 warps x 4u): out = sum_{l,d} band2T*s
// SMEM (71808 B, occ 3):
//   phase A/B: t1hi[80][136]bf16 | t1lo | Chi[80][88] | Clo | band1[32]
//   phase C (overlay after MMA): s[80][132]f32 over t1 region,
//                                band2T[25][128] over C region.
// ============================================================================
#define F_T1H 0
#define F_T1L 21760
#define F_CH  43520
#define F_CL  57600
#define F_BND1 71680
#define F_SMEM 71808           // bytes
// phase-C overlays
#define F_SD  16               // s tile [80][132] f32 (16B offset kept for alignment)
#define F_B2  43520            // band2T [25][128] f32

__global__ __launch_bounds__(320,3) void fused_all(const float* __restrict__ x,
                                                   float* __restrict__ out){
  extern __shared__ char smem[];
  uint32_t sb = smem_u32(smem);
  int tid = threadIdx.x, wid = tid >> 5, lane = tid & 31;
  int p = blockIdx.x, b = blockIdx.y;

  // ---- async C-tile loads (overlap with stencil below) ----
  for (int i = tid; i < 1760; i += 320){
    int var = (i >= 880);
    int j = i - var*880;
    int r = j / 11, ch = j % 11;
    const __nv_bfloat16* src = (var ? g_Clo : g_Chi) + r*88 + ch*8;
    cp16(sb + (var ? F_CL : F_CH) + r*176 + ch*16, src);
  }
  cp_commit();

  // ---- band1[p] into smem (broadcast table for phase A) ----
  float* bnd_s = (float*)(smem + F_BND1);
  if (tid < 25) bnd_s[tid] = g_band1[p*25 + tid];
  __syncthreads();

  // ---- phase A: stage-1 stencil, d-major (low register pressure) ----
  for (int i = tid; i < 512; i += 320){
    int c  = i >> 5;
    int w4 = (i & 31) << 2;
    const float* xs = x + (size_t)(b*CC + c)*PW + w4;
    float4 acck[5];
#pragma unroll
    for (int k = 0; k < KP; k++) acck[k] = make_float4(0.f,0.f,0.f,0.f);
#pragma unroll
    for (int d = -4; d <= 4; d++){
      int h = p + d;
      h = h < 0 ? 0 : (h > 127 ? 127 : h);
      float4 v = *(const float4*)(xs + h*LL);
      int ad = d < 0 ? -d : d;
#pragma unroll
      for (int k = 0; k < KP; k++){
        if (k >= ad){
          float cf = bnd_s[k*k + k + d];
          acck[k].x = fmaf(cf, v.x, acck[k].x);
          acck[k].y = fmaf(cf, v.y, acck[k].y);
          acck[k].z = fmaf(cf, v.z, acck[k].z);
          acck[k].w = fmaf(cf, v.w, acck[k].w);
        }
      }
    }
#pragma unroll
    for (int k = 0; k < KP; k++){
      float4 o = acck[k];
      __nv_bfloat16 h0,l0,h1,l1,h2,l2,h3,l3;
      bsplit(o.x,h0,l0); bsplit(o.y,h1,l1); bsplit(o.z,h2,l2); bsplit(o.w,h3,l3);
      uint2 hv = make_uint2((uint32_t)__bfloat16_as_ushort(h0) | ((uint32_t)__bfloat16_as_ushort(h1)<<16),
                            (uint32_t)__bfloat16_as_ushort(h2) | ((uint32_t)__bfloat16_as_ushort(h3)<<16));
      uint2 lv = make_uint2((uint32_t)__bfloat16_as_ushort(l0) | ((uint32_t)__bfloat16_as_ushort(l1)<<16),
                            (uint32_t)__bfloat16_as_ushort(l2) | ((uint32_t)__bfloat16_as_ushort(l3)<<16));
      uint32_t off = (uint32_t)((k*CC + c)*272 + w4*2);
      *(uint2*)(smem + F_T1H + off) = hv;
      *(uint2*)(smem + F_T1L + off) = lv;
    }
  }

  cp_wait<0>();
  __syncthreads();

  // ---- phase B: HMMA, 10 warps = 5 m-tiles x 2 n-halves, warp tile 16m x 64w
  int mi = wid >> 1, ni = wid & 1;
  float acc[8][4];
#pragma unroll
  for (int nt = 0; nt < 8; nt++)
#pragma unroll
    for (int j = 0; j < 4; j++) acc[nt][j] = 0.f;

  uint32_t arow = (uint32_t)(mi*16 + (lane & 15));
  uint32_t alh  = (uint32_t)((lane >> 4) * 16);
  uint32_t brow16 = (uint32_t)(lane & 15);
  uint32_t blh  = (uint32_t)((lane >> 4) * 16);

#pragma unroll
  for (int kt = 0; kt < 5; kt++){
    uint32_t a_h[4], a_l[4];
    uint32_t aaddr = arow*176 + (uint32_t)kt*32 + alh;
    ldsm4(a_h, sb + F_CH + aaddr);
    ldsm4(a_l, sb + F_CL + aaddr);
#pragma unroll
    for (int g = 0; g < 4; g++){
      uint32_t b_h[4], b_l[4];
      uint32_t baddr = ((uint32_t)kt*16 + brow16)*272 + (uint32_t)(ni*128 + g*32) + blh;
      ldsm4t(b_h, sb + F_T1H + baddr);
      ldsm4t(b_l, sb + F_T1L + baddr);
#pragma unroll
      for (int sub = 0; sub < 2; sub++){
        mma16816(acc[g*2+sub], a_h, b_h + sub*2);
        mma16816(acc[g*2+sub], a_h, b_l + sub*2);
        mma16816(acc[g*2+sub], a_l, b_h + sub*2);
      }
    }
  }

  __syncthreads();   // t1 + C tiles fully consumed; overlays become legal

  // band2T into dead C region (async, overlapped with s-tile writes)
  for (int i = tid; i < 800; i += 320)
    cp16(sb + F_B2 + i*16, g_band2T + i*4);
  cp_commit();

  // accumulators -> s tile [80][132] f32 overlaid on t1 region
  {
    float* sT = (float*)(smem + F_SD);
    int gid = lane >> 2, qc = (lane & 3)*2;
    int row = mi*16 + gid;
#pragma unroll
    for (int nt = 0; nt < 8; nt++){
      int col = ni*64 + nt*8 + qc;
      sT[row*132 + col]       = acc[nt][0];
      sT[row*132 + col + 1]   = acc[nt][1];
      sT[(row+8)*132 + col]   = acc[nt][2];
      sT[(row+8)*132 + col+1] = acc[nt][3];
    }
  }
  cp_wait<0>();
  __syncthreads();

  // ---- phase C: stage-3 stencil, shfl-windowed; warps 0-3 (one per SMSP),
  // each warp handles 4 u values (u = wid + 4*s2) so coef vectors load once
  // per warp and serve 4 outputs. Lanes own q = lane*4..lane*4+3; edge
  // neighbors via shfl (lanes 0/31 garbage x exactly-zero band coefficients).
  if (wid < 4){
    const float* bT = (const float*)(smem + F_B2);    // [25][128]
    const float* sT = (const float*)(smem + F_SD);    // [80][132]
    int q4 = lane*4;
    float o[4][4];
#pragma unroll
    for (int s2 = 0; s2 < 4; s2++)
#pragma unroll
      for (int j = 0; j < 4; j++) o[s2][j] = 0.f;

#pragma unroll
    for (int l = 0; l < KP; l++){
      const int nd = 2*l + 1;
      float4 cj[9];
#pragma unroll
      for (int dd = 0; dd < nd; dd++)
        cj[dd] = *(const float4*)(bT + (l*l + dd)*LL + q4);
#pragma unroll
      for (int s2 = 0; s2 < 4; s2++){
        int u = wid + s2*4;
        const float* srow = sT + (l*UU + u)*132;
        float4 v = *(const float4*)(srow + q4);
        float4 wm, wp;
        wm.x = __shfl_up_sync(0xffffffffu, v.x, 1);
        wm.y = __shfl_up_sync(0xffffffffu, v.y, 1);
        wm.z = __shfl_up_sync(0xffffffffu, v.z, 1);
        wm.w = __shfl_up_sync(0xffffffffu, v.w, 1);
        wp.x = __shfl_down_sync(0xffffffffu, v.x, 1);
        wp.y = __shfl_down_sync(0xffffffffu, v.y, 1);
        wp.z = __shfl_down_sync(0xffffffffu, v.z, 1);
        wp.w = __shfl_down_sync(0xffffffffu, v.w, 1);
        float w[12] = {wm.x,wm.y,wm.z,wm.w, v.x,v.y,v.z,v.w, wp.x,wp.y,wp.z,wp.w};
#pragma unroll
        for (int j = 0; j < 4; j++)
#pragma unroll
          for (int dd = 0; dd < nd; dd++)
            o[s2][j] = fmaf(((const float*)&cj[dd])[j], w[4 + j + dd - l], o[s2][j]);
      }
    }
#pragma unroll
    for (int s2 = 0; s2 < 4; s2++){
      int u = wid + s2*4;
      *(float4*)(out + ((size_t)(b*UU + u)*LL + p)*LL + q4) =
          make_float4(o[s2][0], o[s2][1], o[s2][2], o[s2][3]);
    }
  }
}

// ============================================================================
extern "C" void kernel_launch(void* const* d_in, const int* in_sizes, int n_in,
                              void* d_out, int out_size)
{
  const float* x = nullptr;
  const float* coefs = nullptr;
  const float* cheb1 = nullptr;
  const float* cheb2 = nullptr;
  for (int i = 0; i < n_in; i++){
    int sz = in_sizes[i];
    const float* p = (const float*)d_in[i];
    if (sz == BB*CC*PW)            x = p;
    else if (sz == KP*KP*CC*UU)    coefs = p;
    else if (sz == KP*PW){ if (!cheb1) cheb1 = p; else cheb2 = p; }
  }
  if (!cheb2) cheb2 = cheb1;
  float* out = (float*)d_out;

  cudaFuncSetAttribute(fused_all, cudaFuncAttributeMaxDynamicSharedMemorySize, F_SMEM);

  prep_tabs<<<64, 128>>>(cheb1, cheb2, coefs);
  fused_all<<<dim3(LL, BB), 320, F_SMEM>>>(x, out);
}

// round 12
// speedup vs baseline: 7.9737x; 1.2203x over previous
#include <cuda_runtime.h>
#include <cuda_fp16.h>
#include <cstdint>

#define BB 32
#define CC 16
#define UU 16
#define LL 128
#define PW (LL*LL)
#define KP 5
#define MKC 80
#define MLU 80

// C is scaled by 4096 (exact power of 2); band2T pre-divided by 4096.
#define CSCALE 4096.0f

// ------------------------------- scratch ------------------------------------
__device__ float  g_band1[LL*25];      // packed band of cheb1 [p][25]
__device__ float  g_band2T[25*LL];     // packed band of cheb2 /CSCALE, [j][q]
__device__ __half g_Chi[MLU*88];       // coef*CSCALE fp16 hi [m][kk pad 88]
__device__ __half g_Clo[MLU*88];       // fp16 lo residual

// --------------------------- helpers ------------------------------
__device__ __forceinline__ void cp16(uint32_t dst, const void* src){
  asm volatile("cp.async.cg.shared.global [%0], [%1], 16;" :: "r"(dst), "l"(src));
}
__device__ __forceinline__ void cp_commit(){ asm volatile("cp.async.commit_group;"); }
template<int N> __device__ __forceinline__ void cp_wait(){
  asm volatile("cp.async.wait_group %0;" :: "n"(N));
}
__device__ __forceinline__ uint32_t smem_u32(const void* p){
  return (uint32_t)__cvta_generic_to_shared(p);
}
// pack two floats to fp16x2 (lo in low half)
__device__ __forceinline__ uint32_t f2h2(float lo, float hi){
  uint32_t r;
  asm("cvt.rn.f16x2.f32 %0, %1, %2;" : "=r"(r) : "f"(hi), "f"(lo));
  return r;
}
// m16n8k16 fp16 MMA, fp32 accumulate
__device__ __forceinline__ void mma16816h(float* d, const uint32_t* a, const uint32_t* b){
  asm volatile("mma.sync.aligned.m16n8k16.row.col.f32.f16.f16.f32 "
    "{%0,%1,%2,%3}, {%4,%5,%6,%7}, {%8,%9}, {%0,%1,%2,%3};"
    : "+f"(d[0]),"+f"(d[1]),"+f"(d[2]),"+f"(d[3])
    : "r"(a[0]),"r"(a[1]),"r"(a[2]),"r"(a[3]), "r"(b[0]),"r"(b[1]));
}
__device__ __forceinline__ void ldsm4(uint32_t* r, uint32_t addr){
  asm volatile("ldmatrix.sync.aligned.m8n8.x4.shared.b16 {%0,%1,%2,%3}, [%4];"
    : "=r"(r[0]),"=r"(r[1]),"=r"(r[2]),"=r"(r[3]) : "r"(addr));
}
__device__ __forceinline__ void ldsm4t(uint32_t* r, uint32_t addr){
  asm volatile("ldmatrix.sync.aligned.m8n8.x4.trans.shared.b16 {%0,%1,%2,%3}, [%4];"
    : "=r"(r[0]),"=r"(r[1]),"=r"(r[2]),"=r"(r[3]) : "r"(addr));
}

// ============================================================================
// Prep: band tables (T_k has bandwidth k — exact structural zeros).
// band1[p][k*k+k+d] = c1[k][p+d][p];  band2T[(k*k+k+d)][q] = c2[k][q+d][q]/CSCALE
// C[m=(l,u)][kk=(k1,c)]*CSCALE split to fp16 hi + lo residual, kk padded to 88.
// ============================================================================
__global__ void prep_tabs(const float* __restrict__ c1, const float* __restrict__ c2,
                          const float* __restrict__ coefs){
  int gt = blockIdx.x*128 + threadIdx.x;   // 64 x 128 = 8192
  if (gt < LL){
    int t = gt;
#pragma unroll
    for (int k = 0; k < KP; k++)
      for (int d = -k; d <= k; d++){
        int h = t + d;
        bool ok = (h >= 0 && h < LL);
        g_band1[t*25 + k*k + k + d] = ok ? c1[(k*LL + h)*LL + t] : 0.f;
        g_band2T[(k*k + k + d)*LL + t] = ok ? (c2[(k*LL + h)*LL + t] * (1.0f/CSCALE)) : 0.f;
      }
  }
  for (int i = gt; i < MLU*88; i += 8192){
    int m = i / 88, kk = i % 88;
    float v = 0.f;
    if (kk < MKC){
      int l = m >> 4, u = m & 15, k1 = kk >> 4, c = kk & 15;
      v = coefs[((k1*KP + l)*CC + c)*UU + u] * CSCALE;
    }
    __half h = __float2half_rn(v);
    __half l2 = __float2half_rn(v - __half2float(h));
    g_Chi[i] = h;
    g_Clo[i] = l2;
  }
}

// ============================================================================
// Fully fused kernel, one block per (b, p):
//   phase A (fp32 stencil, d-major): t1[kk][w] -> single fp16 ldsm tile
//   phase B (HMMA fp16 2-product): s[m][w] = (Chi+Clo)[m][kk] * t1f16[kk][w]
//   phase C (shfl-windowed stencil, 4 warps x 4u): out = sum_{l,d} band2T*s
// SMEM (55296 B, occ 3):
//   phase A/B: t1[80][136]h | Chi[80][88]h | Clo[80][88]h | band1[32]f
//   phase C (overlay after MMA): s[80][132]f32 at 16, band2T[25][128] at 42304.
// ============================================================================
#define F_T1  0
#define F_CH  21760
#define F_CL  35840
#define F_BND1 49920
#define F_SMEM 55296           // bytes
// phase-C overlays (legal after post-MMA sync)
#define F_SD  16               // s tile [80][132] f32
#define F_B2  42304            // band2T [25][128] f32

__global__ __launch_bounds__(320,3) void fused_all(const float* __restrict__ x,
                                                   float* __restrict__ out){
  extern __shared__ char smem[];
  uint32_t sb = smem_u32(smem);
  int tid = threadIdx.x, wid = tid >> 5, lane = tid & 31;
  int p = blockIdx.x, b = blockIdx.y;

  // ---- async C-tile loads (overlap with stencil below) ----
  for (int i = tid; i < 1760; i += 320){
    int var = (i >= 880);
    int j = i - var*880;
    int r = j / 11, ch = j % 11;
    const __half* src = (var ? g_Clo : g_Chi) + r*88 + ch*8;
    cp16(sb + (var ? F_CL : F_CH) + r*176 + ch*16, src);
  }
  cp_commit();

  // ---- band1[p] into smem (broadcast table for phase A) ----
  float* bnd_s = (float*)(smem + F_BND1);
  if (tid < 25) bnd_s[tid] = g_band1[p*25 + tid];
  __syncthreads();

  // ---- phase A: stage-1 stencil, d-major; output single fp16 tile ----
  for (int i = tid; i < 512; i += 320){
    int c  = i >> 5;
    int w4 = (i & 31) << 2;
    const float* xs = x + (size_t)(b*CC + c)*PW + w4;
    float4 acck[5];
#pragma unroll
    for (int k = 0; k < KP; k++) acck[k] = make_float4(0.f,0.f,0.f,0.f);
#pragma unroll
    for (int d = -4; d <= 4; d++){
      int h = p + d;
      h = h < 0 ? 0 : (h > 127 ? 127 : h);
      float4 v = *(const float4*)(xs + h*LL);
      int ad = d < 0 ? -d : d;
#pragma unroll
      for (int k = 0; k < KP; k++){
        if (k >= ad){
          float cf = bnd_s[k*k + k + d];
          acck[k].x = fmaf(cf, v.x, acck[k].x);
          acck[k].y = fmaf(cf, v.y, acck[k].y);
          acck[k].z = fmaf(cf, v.z, acck[k].z);
          acck[k].w = fmaf(cf, v.w, acck[k].w);
        }
      }
    }
#pragma unroll
    for (int k = 0; k < KP; k++){
      float4 o = acck[k];
      uint2 hv = make_uint2(f2h2(o.x, o.y), f2h2(o.z, o.w));
      *(uint2*)(smem + F_T1 + (uint32_t)((k*CC + c)*272 + w4*2)) = hv;
    }
  }

  cp_wait<0>();
  __syncthreads();

  // ---- phase B: HMMA fp16, 10 warps = 5m x 2n, warp tile 16m x 64w,
  //      2 products: Chi*t1 + Clo*t1
  int mi = wid >> 1, ni = wid & 1;
  float acc[8][4];
#pragma unroll
  for (int nt = 0; nt < 8; nt++)
#pragma unroll
    for (int j = 0; j < 4; j++) acc[nt][j] = 0.f;

  uint32_t arow = (uint32_t)(mi*16 + (lane & 15));
  uint32_t alh  = (uint32_t)((lane >> 4) * 16);
  uint32_t brow16 = (uint32_t)(lane & 15);
  uint32_t blh  = (uint32_t)((lane >> 4) * 16);

#pragma unroll
  for (int kt = 0; kt < 5; kt++){
    uint32_t a_h[4], a_l[4];
    uint32_t aaddr = arow*176 + (uint32_t)kt*32 + alh;
    ldsm4(a_h, sb + F_CH + aaddr);
    ldsm4(a_l, sb + F_CL + aaddr);
#pragma unroll
    for (int g = 0; g < 4; g++){
      uint32_t b_f[4];
      uint32_t baddr = ((uint32_t)kt*16 + brow16)*272 + (uint32_t)(ni*128 + g*32) + blh;
      ldsm4t(b_f, sb + F_T1 + baddr);
#pragma unroll
      for (int sub = 0; sub < 2; sub++){
        mma16816h(acc[g*2+sub], a_h, b_f + sub*2);
        mma16816h(acc[g*2+sub], a_l, b_f + sub*2);
      }
    }
  }

  __syncthreads();   // t1 + C tiles fully consumed; overlays become legal

  // band2T into overlay region (async, overlapped with s-tile writes)
  for (int i = tid; i < 800; i += 320)
    cp16(sb + F_B2 + i*16, g_band2T + i*4);
  cp_commit();

  // accumulators -> s tile [80][132] f32 (float2 stores)
  {
    float* sT = (float*)(smem + F_SD);
    int gid = lane >> 2, qc = (lane & 3)*2;
    int row = mi*16 + gid;
#pragma unroll
    for (int nt = 0; nt < 8; nt++){
      int col = ni*64 + nt*8 + qc;
      *(float2*)(sT + row*132 + col)     = make_float2(acc[nt][0], acc[nt][1]);
      *(float2*)(sT + (row+8)*132 + col) = make_float2(acc[nt][2], acc[nt][3]);
    }
  }
  cp_wait<0>();
  __syncthreads();

  // ---- phase C: stage-3 stencil, shfl-windowed; warps 0-3 (one per SMSP),
  // each warp handles 4 u values (u = wid + 4*s2); coef vectors load once per
  // warp and serve 4 outputs. Lanes own q = lane*4..lane*4+3; edge neighbors
  // via shfl (lanes 0/31 garbage x exactly-zero band coefficients).
  if (wid < 4){
    const float* bT = (const float*)(smem + F_B2);    // [25][128]
    const float* sT = (const float*)(smem + F_SD);    // [80][132]
    int q4 = lane*4;
    float o[4][4];
#pragma unroll
    for (int s2 = 0; s2 < 4; s2++)
#pragma unroll
      for (int j = 0; j < 4; j++) o[s2][j] = 0.f;

#pragma unroll
    for (int l = 0; l < KP; l++){
      const int nd = 2*l + 1;
      float4 cj[9];
#pragma unroll
      for (int dd = 0; dd < nd; dd++)
        cj[dd] = *(const float4*)(bT + (l*l + dd)*LL + q4);
#pragma unroll
      for (int s2 = 0; s2 < 4; s2++){
        int u = wid + s2*4;
        const float* srow = sT + (l*UU + u)*132;
        float4 v = *(const float4*)(srow + q4);
        float4 wm, wp;
        wm.x = __shfl_up_sync(0xffffffffu, v.x, 1);
        wm.y = __shfl_up_sync(0xffffffffu, v.y, 1);
        wm.z = __shfl_up_sync(0xffffffffu, v.z, 1);
        wm.w = __shfl_up_sync(0xffffffffu, v.w, 1);
        wp.x = __shfl_down_sync(0xffffffffu, v.x, 1);
        wp.y = __shfl_down_sync(0xffffffffu, v.y, 1);
        wp.z = __shfl_down_sync(0xffffffffu, v.z, 1);
        wp.w = __shfl_down_sync(0xffffffffu, v.w, 1);
        float w[12] = {wm.x,wm.y,wm.z,wm.w, v.x,v.y,v.z,v.w, wp.x,wp.y,wp.z,wp.w};
#pragma unroll
        for (int j = 0; j < 4; j++)
#pragma unroll
          for (int dd = 0; dd < nd; dd++)
            o[s2][j] = fmaf(((const float*)&cj[dd])[j], w[4 + j + dd - l], o[s2][j]);
      }
    }
#pragma unroll
    for (int s2 = 0; s2 < 4; s2++){
      int u = wid + s2*4;
      *(float4*)(out + ((size_t)(b*UU + u)*LL + p)*LL + q4) =
          make_float4(o[s2][0], o[s2][1], o[s2][2], o[s2][3]);
    }
  }
}

// ============================================================================
extern "C" void kernel_launch(void* const* d_in, const int* in_sizes, int n_in,
                              void* d_out, int out_size)
{
  const float* x = nullptr;
  const float* coefs = nullptr;
  const float* cheb1 = nullptr;
  const float* cheb2 = nullptr;
  for (int i = 0; i < n_in; i++){
    int sz = in_sizes[i];
    const float* p = (const float*)d_in[i];
    if (sz == BB*CC*PW)            x = p;
    else if (sz == KP*KP*CC*UU)    coefs = p;
    else if (sz == KP*PW){ if (!cheb1) cheb1 = p; else cheb2 = p; }
  }
  if (!cheb2) cheb2 = cheb1;
  float* out = (float*)d_out;

  cudaFuncSetAttribute(fused_all, cudaFuncAttributeMaxDynamicSharedMemorySize, F_SMEM);

  prep_tabs<<<64, 128>>>(cheb1, cheb2, coefs);
  fused_all<<<dim3(LL, BB), 320, F_SMEM>>>(x, out);
}

// round 13
// speedup vs baseline: 8.8319x; 1.1076x over previous
#include <cuda_runtime.h>
#include <cuda_fp16.h>
#include <cstdint>

#define BB 32
#define CC 16
#define UU 16
#define LL 128
#define PW (LL*LL)
#define KP 5
#define MKC 80
#define MLU 80

// C is scaled by 4096 (exact power of 2); band2T pre-divided by 4096.
#define CSCALE 4096.0f

// ------------------------------- scratch ------------------------------------
__device__ float  g_band1[LL*25];      // packed band of cheb1 [p][25]
__device__ float  g_band2T[25*LL];     // packed band of cheb2 /CSCALE, [j][q]
__device__ __half g_Chi[MLU*88];       // coef*CSCALE fp16 [m][kk pad 88]

// --------------------------- helpers ------------------------------
__device__ __forceinline__ void cp16(uint32_t dst, const void* src){
  asm volatile("cp.async.cg.shared.global [%0], [%1], 16;" :: "r"(dst), "l"(src));
}
__device__ __forceinline__ void cp_commit(){ asm volatile("cp.async.commit_group;"); }
template<int N> __device__ __forceinline__ void cp_wait(){
  asm volatile("cp.async.wait_group %0;" :: "n"(N));
}
__device__ __forceinline__ uint32_t smem_u32(const void* p){
  return (uint32_t)__cvta_generic_to_shared(p);
}
// pack two floats to fp16x2 (lo arg in low half)
__device__ __forceinline__ uint32_t f2h2(float lo, float hi){
  uint32_t r;
  asm("cvt.rn.f16x2.f32 %0, %1, %2;" : "=r"(r) : "f"(hi), "f"(lo));
  return r;
}
// m16n8k16 fp16 MMA, fp32 accumulate
__device__ __forceinline__ void mma16816h(float* d, const uint32_t* a, const uint32_t* b){
  asm volatile("mma.sync.aligned.m16n8k16.row.col.f32.f16.f16.f32 "
    "{%0,%1,%2,%3}, {%4,%5,%6,%7}, {%8,%9}, {%0,%1,%2,%3};"
    : "+f"(d[0]),"+f"(d[1]),"+f"(d[2]),"+f"(d[3])
    : "r"(a[0]),"r"(a[1]),"r"(a[2]),"r"(a[3]), "r"(b[0]),"r"(b[1]));
}
__device__ __forceinline__ void ldsm4(uint32_t* r, uint32_t addr){
  asm volatile("ldmatrix.sync.aligned.m8n8.x4.shared.b16 {%0,%1,%2,%3}, [%4];"
    : "=r"(r[0]),"=r"(r[1]),"=r"(r[2]),"=r"(r[3]) : "r"(addr));
}
__device__ __forceinline__ void ldsm4t(uint32_t* r, uint32_t addr){
  asm volatile("ldmatrix.sync.aligned.m8n8.x4.trans.shared.b16 {%0,%1,%2,%3}, [%4];"
    : "=r"(r[0]),"=r"(r[1]),"=r"(r[2]),"=r"(r[3]) : "r"(addr));
}

// ============================================================================
// Prep: band tables (T_k has bandwidth k — exact structural zeros).
// band1[p][k*k+k+d] = c1[k][p+d][p];  band2T[(k*k+k+d)][q] = c2[k][q+d][q]/CSCALE
// C[m=(l,u)][kk=(k1,c)]*CSCALE -> fp16, kk padded to 88.
// ============================================================================
__global__ void prep_tabs(const float* __restrict__ c1, const float* __restrict__ c2,
                          const float* __restrict__ coefs){
  int gt = blockIdx.x*128 + threadIdx.x;   // 64 x 128 = 8192
  if (gt < LL){
    int t = gt;
#pragma unroll
    for (int k = 0; k < KP; k++)
      for (int d = -k; d <= k; d++){
        int h = t + d;
        bool ok = (h >= 0 && h < LL);
        g_band1[t*25 + k*k + k + d] = ok ? c1[(k*LL + h)*LL + t] : 0.f;
        g_band2T[(k*k + k + d)*LL + t] = ok ? (c2[(k*LL + h)*LL + t] * (1.0f/CSCALE)) : 0.f;
      }
  }
  for (int i = gt; i < MLU*88; i += 8192){
    int m = i / 88, kk = i % 88;
    float v = 0.f;
    if (kk < MKC){
      int l = m >> 4, u = m & 15, k1 = kk >> 4, c = kk & 15;
      v = coefs[((k1*KP + l)*CC + c)*UU + u] * CSCALE;
    }
    g_Chi[i] = __float2half_rn(v);
  }
}

// ============================================================================
// Fully fused kernel, one block per (b, p):
//   phase A (fp32 stencil, d-major): t1[kk][w] -> single fp16 ldsm tile
//   phase B (HMMA fp16, single product): s[m][w] = Chi[m][kk] * t1f16[kk][w]
//   phase C (shfl-windowed stencil, 4 warps x 4u): out = sum_{l,d} band2T*s
// SMEM (55296 B, occ 3):
//   phase A/B: t1[80][136]h | Chi[80][88]h | band1[32]f
//   phase C (overlay after MMA): s[80][132]f32 at 16, band2T[25][128] at 42304.
// ============================================================================
#define F_T1  0
#define F_CH  21760
#define F_BND1 35840
#define F_SMEM 55296           // bytes (phase-C s-tile overlay is high-water mark)
// phase-C overlays (legal after post-MMA sync)
#define F_SD  16               // s tile [80][132] f32
#define F_B2  42304            // band2T [25][128] f32

__global__ __launch_bounds__(320,3) void fused_all(const float* __restrict__ x,
                                                   float* __restrict__ out){
  extern __shared__ char smem[];
  uint32_t sb = smem_u32(smem);
  int tid = threadIdx.x, wid = tid >> 5, lane = tid & 31;
  int p = blockIdx.x, b = blockIdx.y;

  // ---- async C-tile loads (overlap with stencil below) ----
  for (int i = tid; i < 880; i += 320){
    int r = i / 11, ch = i % 11;
    cp16(sb + F_CH + r*176 + ch*16, g_Chi + r*88 + ch*8);
  }
  cp_commit();

  // ---- band1[p] into smem (broadcast table for phase A) ----
  float* bnd_s = (float*)(smem + F_BND1);
  if (tid < 25) bnd_s[tid] = g_band1[p*25 + tid];
  __syncthreads();

  // ---- phase A: stage-1 stencil, d-major; output single fp16 tile ----
  for (int i = tid; i < 512; i += 320){
    int c  = i >> 5;
    int w4 = (i & 31) << 2;
    const float* xs = x + (size_t)(b*CC + c)*PW + w4;
    float4 acck[5];
#pragma unroll
    for (int k = 0; k < KP; k++) acck[k] = make_float4(0.f,0.f,0.f,0.f);
#pragma unroll
    for (int d = -4; d <= 4; d++){
      int h = p + d;
      h = h < 0 ? 0 : (h > 127 ? 127 : h);
      float4 v = *(const float4*)(xs + h*LL);
      int ad = d < 0 ? -d : d;
#pragma unroll
      for (int k = 0; k < KP; k++){
        if (k >= ad){
          float cf = bnd_s[k*k + k + d];
          acck[k].x = fmaf(cf, v.x, acck[k].x);
          acck[k].y = fmaf(cf, v.y, acck[k].y);
          acck[k].z = fmaf(cf, v.z, acck[k].z);
          acck[k].w = fmaf(cf, v.w, acck[k].w);
        }
      }
    }
#pragma unroll
    for (int k = 0; k < KP; k++){
      float4 o = acck[k];
      uint2 hv = make_uint2(f2h2(o.x, o.y), f2h2(o.z, o.w));
      *(uint2*)(smem + F_T1 + (uint32_t)((k*CC + c)*272 + w4*2)) = hv;
    }
  }

  cp_wait<0>();
  __syncthreads();

  // ---- phase B: HMMA fp16 single-product, 10 warps = 5m x 2n,
  //      warp tile 16m x 64w
  int mi = wid >> 1, ni = wid & 1;
  float acc[8][4];
#pragma unroll
  for (int nt = 0; nt < 8; nt++)
#pragma unroll
    for (int j = 0; j < 4; j++) acc[nt][j] = 0.f;

  uint32_t arow = (uint32_t)(mi*16 + (lane & 15));
  uint32_t alh  = (uint32_t)((lane >> 4) * 16);
  uint32_t brow16 = (uint32_t)(lane & 15);
  uint32_t blh  = (uint32_t)((lane >> 4) * 16);

#pragma unroll
  for (int kt = 0; kt < 5; kt++){
    uint32_t a_h[4];
    ldsm4(a_h, sb + F_CH + arow*176 + (uint32_t)kt*32 + alh);
#pragma unroll
    for (int g = 0; g < 4; g++){
      uint32_t b_f[4];
      uint32_t baddr = ((uint32_t)kt*16 + brow16)*272 + (uint32_t)(ni*128 + g*32) + blh;
      ldsm4t(b_f, sb + F_T1 + baddr);
      mma16816h(acc[g*2+0], a_h, b_f + 0);
      mma16816h(acc[g*2+1], a_h, b_f + 2);
    }
  }

  __syncthreads();   // t1 + C tiles fully consumed; overlays become legal

  // band2T into overlay region (async, overlapped with s-tile writes)
  for (int i = tid; i < 800; i += 320)
    cp16(sb + F_B2 + i*16, g_band2T + i*4);
  cp_commit();

  // accumulators -> s tile [80][132] f32 (float2 stores)
  {
    float* sT = (float*)(smem + F_SD);
    int gid = lane >> 2, qc = (lane & 3)*2;
    int row = mi*16 + gid;
#pragma unroll
    for (int nt = 0; nt < 8; nt++){
      int col = ni*64 + nt*8 + qc;
      *(float2*)(sT + row*132 + col)     = make_float2(acc[nt][0], acc[nt][1]);
      *(float2*)(sT + (row+8)*132 + col) = make_float2(acc[nt][2], acc[nt][3]);
    }
  }
  cp_wait<0>();
  __syncthreads();

  // ---- phase C: stage-3 stencil, shfl-windowed; warps 0-3 (one per SMSP),
  // each warp handles 4 u values (u = wid + 4*s2); coef vectors load once per
  // warp and serve 4 outputs. Lanes own q = lane*4..lane*4+3; edge neighbors
  // via shfl (lanes 0/31 garbage x exactly-zero band coefficients).
  if (wid < 4){
    const float* bT = (const float*)(smem + F_B2);    // [25][128]
    const float* sT = (const float*)(smem + F_SD);    // [80][132]
    int q4 = lane*4;
    float o[4][4];
#pragma unroll
    for (int s2 = 0; s2 < 4; s2++)
#pragma unroll
      for (int j = 0; j < 4; j++) o[s2][j] = 0.f;

#pragma unroll
    for (int l = 0; l < KP; l++){
      const int nd = 2*l + 1;
      float4 cj[9];
#pragma unroll
      for (int dd = 0; dd < nd; dd++)
        cj[dd] = *(const float4*)(bT + (l*l + dd)*LL + q4);
#pragma unroll
      for (int s2 = 0; s2 < 4; s2++){
        int u = wid + s2*4;
        const float* srow = sT + (l*UU + u)*132;
        float4 v = *(const float4*)(srow + q4);
        float4 wm, wp;
        wm.x = __shfl_up_sync(0xffffffffu, v.x, 1);
        wm.y = __shfl_up_sync(0xffffffffu, v.y, 1);
        wm.z = __shfl_up_sync(0xffffffffu, v.z, 1);
        wm.w = __shfl_up_sync(0xffffffffu, v.w, 1);
        wp.x = __shfl_down_sync(0xffffffffu, v.x, 1);
        wp.y = __shfl_down_sync(0xffffffffu, v.y, 1);
        wp.z = __shfl_down_sync(0xffffffffu, v.z, 1);
        wp.w = __shfl_down_sync(0xffffffffu, v.w, 1);
        float w[12] = {wm.x,wm.y,wm.z,wm.w, v.x,v.y,v.z,v.w, wp.x,wp.y,wp.z,wp.w};
#pragma unroll
        for (int j = 0; j < 4; j++)
#pragma unroll
          for (int dd = 0; dd < nd; dd++)
            o[s2][j] = fmaf(((const float*)&cj[dd])[j], w[4 + j + dd - l], o[s2][j]);
      }
    }
#pragma unroll
    for (int s2 = 0; s2 < 4; s2++){
      int u = wid + s2*4;
      *(float4*)(out + ((size_t)(b*UU + u)*LL + p)*LL + q4) =
          make_float4(o[s2][0], o[s2][1], o[s2][2], o[s2][3]);
    }
  }
}

// ============================================================================
extern "C" void kernel_launch(void* const* d_in, const int* in_sizes, int n_in,
                              void* d_out, int out_size)
{
  const float* x = nullptr;
  const float* coefs = nullptr;
  const float* cheb1 = nullptr;
  const float* cheb2 = nullptr;
  for (int i = 0; i < n_in; i++){
    int sz = in_sizes[i];
    const float* p = (const float*)d_in[i];
    if (sz == BB*CC*PW)            x = p;
    else if (sz == KP*KP*CC*UU)    coefs = p;
    else if (sz == KP*PW){ if (!cheb1) cheb1 = p; else cheb2 = p; }
  }
  if (!cheb2) cheb2 = cheb1;
  float* out = (float*)d_out;

  cudaFuncSetAttribute(fused_all, cudaFuncAttributeMaxDynamicSharedMemorySize, F_SMEM);

  prep_tabs<<<64, 128>>>(cheb1, cheb2, coefs);
  fused_all<<<dim3(LL, BB), 320, F_SMEM>>>(x, out);
}